// round 13
// baseline (speedup 1.0000x reference)
#include <cuda_runtime.h>
#include <cuda_fp16.h>
#include <math.h>

// ---------------------------------------------------------------------------
// GIN_37048387895934 — fused ELL-gather+MLP layers, f32x2 math.
// fp16 inter-layer STORAGE, fp32 ACCUMULATION. Single-pass ELL build.
// Gather loops run a WARP-UNIFORM trip count (dmax = warp-max degree) so all
// __shfl_sync calls are convergent; feature loads predicated per-group.
// N=524288 nodes, E=8388608 edges, DIM=32, 8192 graphs x 64 nodes.
// ---------------------------------------------------------------------------

#define NFEAT 16
#define HDIM 32
#define NPG 64
#define BN_EPS 1e-5f
#define ELL_CAP 64  // Poisson(16): P(deg>64) ~ 3e-20 per node

typedef unsigned long long ull;
typedef unsigned int uint;

static constexpr int MAX_NODES = 8192 * 64;       // 524288

__device__ __align__(256) uint g_bufA[(size_t)MAX_NODES * HDIM / 2];  // fp16 rows
__device__ __align__(256) uint g_bufB[(size_t)MAX_NODES * HDIM / 2];  // fp16 rows
__device__ int g_cnt[MAX_NODES];                                      // degree
__device__ __align__(16) int g_colell[(size_t)MAX_NODES * ELL_CAP];   // ELL columns
__device__ float g_stats[3 * 2 * HDIM];
__device__ __align__(16) float g_Wmod[HDIM * HDIM];
__device__ float g_cvec[HDIM];
__device__ float g_scsh[2 * HDIM];

// ---------------------------------------------------------------------------
// Packed math helpers.
// ---------------------------------------------------------------------------
__device__ __forceinline__ ull pack2(float x, float y) {
    ull r;
    asm("mov.b64 %0, {%1, %2};" : "=l"(r) : "f"(x), "f"(y));
    return r;
}
__device__ __forceinline__ void unpack2(ull v, float& x, float& y) {
    asm("mov.b64 {%0, %1}, %2;" : "=f"(x), "=f"(y) : "l"(v));
}
__device__ __forceinline__ ull fma2(ull a, ull b, ull c) {
    ull d;
    asm("fma.rn.f32x2 %0, %1, %2, %3;" : "=l"(d) : "l"(a), "l"(b), "l"(c));
    return d;
}
__device__ __forceinline__ ull add2(ull a, ull b) {
    ull d;
    asm("add.rn.f32x2 %0, %1, %2;" : "=l"(d) : "l"(a), "l"(b));
    return d;
}
// Accumulate a uint4 of 8 fp16 values into 4 packed-f32x2 accumulators.
__device__ __forceinline__ void hacc(uint4 u, ull& x0, ull& x1, ull& x2, ull& x3) {
    float2 f;
    f = __half22float2(*(__half2*)&u.x);
    x0 = add2(x0, pack2(f.x, f.y));
    f = __half22float2(*(__half2*)&u.y);
    x1 = add2(x1, pack2(f.x, f.y));
    f = __half22float2(*(__half2*)&u.z);
    x2 = add2(x2, pack2(f.x, f.y));
    f = __half22float2(*(__half2*)&u.w);
    x3 = add2(x3, pack2(f.x, f.y));
}
// Warp-max of v (groups of 4 share v; offsets 4/8/16 cover the 8 groups).
__device__ __forceinline__ int warp_max_deg(int v) {
    v = max(v, __shfl_xor_sync(0xFFFFFFFFu, v, 4));
    v = max(v, __shfl_xor_sync(0xFFFFFFFFu, v, 8));
    v = max(v, __shfl_xor_sync(0xFFFFFFFFu, v, 16));
    return v;
}

// ---------------------------------------------------------------------------
// ELL build: single pass, no histogram/scan.
// ---------------------------------------------------------------------------
__global__ void place_kernel(const int* __restrict__ src, const int* __restrict__ dst,
                             int* __restrict__ cnt, int* __restrict__ colell,
                             int n_edges) {
    int e = blockIdx.x * blockDim.x + threadIdx.x;
    if (e < n_edges) {
        int d = __ldcs(&dst[e]);
        int p = atomicAdd(&cnt[d], 1);
        p = min(p, ELL_CAP - 1);  // statistically unreachable; avoids OOB
        colell[(size_t)d * ELL_CAP + p] = __ldcs(&src[e]);
    }
}

// ---------------------------------------------------------------------------
// Layer 1 fused: gather 16-dim fp32 x + MLP (W1a folded) + stats.
// Block = 256 nodes. Gather: 8 warps x 4 passes x 8 nodes, 4 lanes/node.
// ---------------------------------------------------------------------------
__global__ __launch_bounds__(256, 5) void layer1_kernel(
    const ulonglong2* __restrict__ x4, const int* __restrict__ cnt,
    const int* __restrict__ colell,
    const float* __restrict__ Wa, const float* __restrict__ ba,
    const float* __restrict__ Wb, const float* __restrict__ bb,
    uint* __restrict__ vouth, float* __restrict__ stats, int n_nodes) {
    __shared__ float tile[256 * 33];
    __shared__ __align__(16) ull sWa2[NFEAT * HDIM / 2];
    __shared__ __align__(16) ull sWb2[HDIM * HDIM / 2];
    __shared__ float sba[HDIM], sbb[HDIM];
    __shared__ float ps[8 * 32], pq[8 * 32];

    int tid = threadIdx.x;
    int warp = tid >> 5, lane = tid & 31;
    int g = lane >> 2, q = lane & 3;
    int base = blockIdx.x * 256;

    for (int i = tid; i < NFEAT * HDIM / 2; i += 256) sWa2[i] = ((const ull*)Wa)[i];
    for (int i = tid; i < HDIM * HDIM / 2; i += 256) sWb2[i] = ((const ull*)Wb)[i];
    if (tid < HDIM) {
        sba[tid] = ba[tid];
        sbb[tid] = bb[tid];
    }

    // ---- Gather phase (warp-uniform trip count) ----
    for (int pass = 0; pass < 4; pass++) {
        int row = warp * 32 + pass * 8 + g;
        int node = base + row;
        bool valid = node < n_nodes;
        int cnode = valid ? node : (n_nodes - 1);
        int deg = min(__ldg(&cnt[cnode]), ELL_CAP);
        int dmax = warp_max_deg(deg);
        const int4* cb4 = (const int4*)(colell + (size_t)cnode * ELL_CAP);

        ulonglong2 self = __ldg(&x4[(size_t)cnode * 4 + q]);
        ull a0 = self.x, a1 = self.y;
        ull b0 = 0, b1 = 0;

        for (int b = 0; b < dmax; b += 16) {
            int4 i4 = __ldg(&cb4[(b >> 2) + q]);  // in-row for b<64; no guard
#pragma unroll
            for (int j = 0; j < 16; j += 4) {
                int o = j >> 2;
                int s0 = __shfl_sync(0xFFFFFFFFu, i4.x, o, 4);
                int s1 = __shfl_sync(0xFFFFFFFFu, i4.y, o, 4);
                int s2 = __shfl_sync(0xFFFFFFFFu, i4.z, o, 4);
                int s3 = __shfl_sync(0xFFFFFFFFu, i4.w, o, 4);
                if (b + j + 0 < deg) {
                    ulonglong2 u = __ldg(&x4[(size_t)s0 * 4 + q]);
                    a0 = add2(a0, u.x);
                    a1 = add2(a1, u.y);
                }
                if (b + j + 1 < deg) {
                    ulonglong2 u = __ldg(&x4[(size_t)s1 * 4 + q]);
                    b0 = add2(b0, u.x);
                    b1 = add2(b1, u.y);
                }
                if (b + j + 2 < deg) {
                    ulonglong2 u = __ldg(&x4[(size_t)s2 * 4 + q]);
                    a0 = add2(a0, u.x);
                    a1 = add2(a1, u.y);
                }
                if (b + j + 3 < deg) {
                    ulonglong2 u = __ldg(&x4[(size_t)s3 * 4 + q]);
                    b0 = add2(b0, u.x);
                    b1 = add2(b1, u.y);
                }
            }
        }
        float f0, f1, f2, f3;
        unpack2(add2(a0, b0), f0, f1);
        unpack2(add2(a1, b1), f2, f3);
        float* tr = &tile[row * 33 + 4 * q];
        tr[0] = valid ? f0 : 0.0f;
        tr[1] = valid ? f1 : 0.0f;
        tr[2] = valid ? f2 : 0.0f;
        tr[3] = valid ? f3 : 0.0f;
    }
    __syncthreads();

    // ---- MLP phase ----
    bool valid = (base + tid) < n_nodes;
    ull u2[16];
#pragma unroll
    for (int j = 0; j < 16; j++) u2[j] = pack2(sba[2 * j], sba[2 * j + 1]);
#pragma unroll
    for (int i = 0; i < NFEAT; i++) {
        float ti = tile[tid * 33 + i];
        ull tt = pack2(ti, ti);
#pragma unroll
        for (int j = 0; j < 8; j++) {
            ulonglong2 w = *(const ulonglong2*)&sWa2[i * 16 + 2 * j];
            u2[2 * j] = fma2(tt, w.x, u2[2 * j]);
            u2[2 * j + 1] = fma2(tt, w.y, u2[2 * j + 1]);
        }
    }
    // relu(u) -> own tile row (frees u2 for reuse as v accumulators)
#pragma unroll
    for (int j = 0; j < 16; j++) {
        float a, b;
        unpack2(u2[j], a, b);
        tile[tid * 33 + 2 * j] = fmaxf(a, 0.0f);
        tile[tid * 33 + 2 * j + 1] = fmaxf(b, 0.0f);
    }
#pragma unroll
    for (int j = 0; j < 16; j++) u2[j] = pack2(sbb[2 * j], sbb[2 * j + 1]);
#pragma unroll
    for (int i = 0; i < HDIM; i++) {
        float ti = tile[tid * 33 + i];
        ull tt = pack2(ti, ti);
#pragma unroll
        for (int j = 0; j < 8; j++) {
            ulonglong2 w = *(const ulonglong2*)&sWb2[i * 16 + 2 * j];
            u2[2 * j] = fma2(tt, w.x, u2[2 * j]);
            u2[2 * j + 1] = fma2(tt, w.y, u2[2 * j + 1]);
        }
    }
#pragma unroll
    for (int j = 0; j < 16; j++) {
        float a, b;
        unpack2(u2[j], a, b);
        tile[tid * 33 + 2 * j] = valid ? fmaxf(a, 0.0f) : 0.0f;
        tile[tid * 33 + 2 * j + 1] = valid ? fmaxf(b, 0.0f) : 0.0f;
    }
    __syncthreads();

    // fp16 store + stats column reduction
#pragma unroll
    for (int k = 0; k < 16; k++) {
        int rr = warp * 32 + 2 * k + (lane >> 4);
        int node = base + rr;
        int wd = lane & 15;
        if (node < n_nodes) {
            float2 f;
            f.x = tile[rr * 33 + 2 * wd];
            f.y = tile[rr * 33 + 2 * wd + 1];
            __half2 h = __float22half2_rn(f);
            vouth[(size_t)node * 16 + wd] = *(uint*)&h;
        }
    }
    float s = 0.0f, qq2 = 0.0f;
#pragma unroll
    for (int k = 0; k < 32; k++) {
        float vv = tile[(warp * 32 + k) * 33 + lane];
        s += vv;
        qq2 += vv * vv;
    }
    ps[warp * 32 + lane] = s;
    pq[warp * 32 + lane] = qq2;
    __syncthreads();
    if (tid < 32) {
        float ss = 0.0f, qs = 0.0f;
#pragma unroll
        for (int k = 0; k < 8; k++) {
            ss += ps[k * 32 + tid];
            qs += pq[k * 32 + tid];
        }
        atomicAdd(&stats[tid], ss);
        atomicAdd(&stats[32 + tid], qs);
    }
}

// ---------------------------------------------------------------------------
// Layers 2/3 fused: gather 32-dim fp16 rows (fp32 accumulate) + MLP with
// previous BN folded (Wmod/cvec, needs deg) + stats. fp16 output.
// ---------------------------------------------------------------------------
__global__ __launch_bounds__(256, 5) void layer23_kernel(
    const uint4* __restrict__ vinh4, const int* __restrict__ cnt,
    const int* __restrict__ colell,
    const float* __restrict__ Wmod, const float* __restrict__ cvec,
    const float* __restrict__ ba, const float* __restrict__ Wb,
    const float* __restrict__ bb, uint* __restrict__ vouth,
    float* __restrict__ stats, int n_nodes) {
    __shared__ float tile[256 * 33];
    __shared__ __align__(16) ull sWa2[HDIM * HDIM / 2];
    __shared__ __align__(16) ull sWb2[HDIM * HDIM / 2];
    __shared__ float sba[HDIM], sbb[HDIM], scv[HDIM];
    __shared__ float ps[8 * 32], pq[8 * 32];

    int tid = threadIdx.x;
    int warp = tid >> 5, lane = tid & 31;
    int g = lane >> 2, q = lane & 3;
    int base = blockIdx.x * 256;

    for (int i = tid; i < HDIM * HDIM / 2; i += 256) {
        sWa2[i] = ((const ull*)Wmod)[i];
        sWb2[i] = ((const ull*)Wb)[i];
    }
    if (tid < HDIM) {
        sba[tid] = ba[tid];
        sbb[tid] = bb[tid];
        scv[tid] = cvec[tid];
    }

    // ---- Gather phase (warp-uniform trip count) ----
    for (int pass = 0; pass < 4; pass++) {
        int row = warp * 32 + pass * 8 + g;
        int node = base + row;
        bool valid = node < n_nodes;
        int cnode = valid ? node : (n_nodes - 1);
        int deg = min(__ldg(&cnt[cnode]), ELL_CAP);
        int dmax = warp_max_deg(deg);
        const int4* cb4 = (const int4*)(colell + (size_t)cnode * ELL_CAP);

        ull a0 = 0, a1 = 0, a2 = 0, a3 = 0;
        ull b0 = 0, b1 = 0, b2 = 0, b3 = 0;
        hacc(__ldg(&vinh4[(size_t)cnode * 4 + q]), a0, a1, a2, a3);  // self

        for (int b = 0; b < dmax; b += 16) {
            int4 i4 = __ldg(&cb4[(b >> 2) + q]);
#pragma unroll
            for (int j = 0; j < 16; j += 4) {
                int o = j >> 2;
                int s0 = __shfl_sync(0xFFFFFFFFu, i4.x, o, 4);
                int s1 = __shfl_sync(0xFFFFFFFFu, i4.y, o, 4);
                int s2 = __shfl_sync(0xFFFFFFFFu, i4.z, o, 4);
                int s3 = __shfl_sync(0xFFFFFFFFu, i4.w, o, 4);
                if (b + j + 0 < deg) hacc(__ldg(&vinh4[(size_t)s0 * 4 + q]), a0, a1, a2, a3);
                if (b + j + 1 < deg) hacc(__ldg(&vinh4[(size_t)s1 * 4 + q]), b0, b1, b2, b3);
                if (b + j + 2 < deg) hacc(__ldg(&vinh4[(size_t)s2 * 4 + q]), a0, a1, a2, a3);
                if (b + j + 3 < deg) hacc(__ldg(&vinh4[(size_t)s3 * 4 + q]), b0, b1, b2, b3);
            }
        }
        float* tr = &tile[row * 33 + 8 * q];
        float fa, fb;
        unpack2(add2(a0, b0), fa, fb);
        tr[0] = valid ? fa : 0.0f;
        tr[1] = valid ? fb : 0.0f;
        unpack2(add2(a1, b1), fa, fb);
        tr[2] = valid ? fa : 0.0f;
        tr[3] = valid ? fb : 0.0f;
        unpack2(add2(a2, b2), fa, fb);
        tr[4] = valid ? fa : 0.0f;
        tr[5] = valid ? fb : 0.0f;
        unpack2(add2(a3, b3), fa, fb);
        tr[6] = valid ? fa : 0.0f;
        tr[7] = valid ? fb : 0.0f;
        if (q == 0) tile[row * 33 + 32] = (float)deg;
    }
    __syncthreads();

    // ---- MLP phase ----
    bool valid = (base + tid) < n_nodes;
    float degp1 = tile[tid * 33 + 32] + 1.0f;
    ull u2[16];
#pragma unroll
    for (int j = 0; j < 16; j++)
        u2[j] = pack2(fmaf(degp1, scv[2 * j], sba[2 * j]),
                      fmaf(degp1, scv[2 * j + 1], sba[2 * j + 1]));
#pragma unroll
    for (int i = 0; i < HDIM; i++) {
        float ti = tile[tid * 33 + i];
        ull tt = pack2(ti, ti);
#pragma unroll
        for (int j = 0; j < 8; j++) {
            ulonglong2 w = *(const ulonglong2*)&sWa2[i * 16 + 2 * j];
            u2[2 * j] = fma2(tt, w.x, u2[2 * j]);
            u2[2 * j + 1] = fma2(tt, w.y, u2[2 * j + 1]);
        }
    }
#pragma unroll
    for (int j = 0; j < 16; j++) {
        float a, b;
        unpack2(u2[j], a, b);
        tile[tid * 33 + 2 * j] = fmaxf(a, 0.0f);
        tile[tid * 33 + 2 * j + 1] = fmaxf(b, 0.0f);
    }
#pragma unroll
    for (int j = 0; j < 16; j++) u2[j] = pack2(sbb[2 * j], sbb[2 * j + 1]);
#pragma unroll
    for (int i = 0; i < HDIM; i++) {
        float ti = tile[tid * 33 + i];
        ull tt = pack2(ti, ti);
#pragma unroll
        for (int j = 0; j < 8; j++) {
            ulonglong2 w = *(const ulonglong2*)&sWb2[i * 16 + 2 * j];
            u2[2 * j] = fma2(tt, w.x, u2[2 * j]);
            u2[2 * j + 1] = fma2(tt, w.y, u2[2 * j + 1]);
        }
    }
#pragma unroll
    for (int j = 0; j < 16; j++) {
        float a, b;
        unpack2(u2[j], a, b);
        tile[tid * 33 + 2 * j] = valid ? fmaxf(a, 0.0f) : 0.0f;
        tile[tid * 33 + 2 * j + 1] = valid ? fmaxf(b, 0.0f) : 0.0f;
    }
    __syncthreads();

#pragma unroll
    for (int k = 0; k < 16; k++) {
        int rr = warp * 32 + 2 * k + (lane >> 4);
        int node = base + rr;
        int wd = lane & 15;
        if (node < n_nodes) {
            float2 f;
            f.x = tile[rr * 33 + 2 * wd];
            f.y = tile[rr * 33 + 2 * wd + 1];
            __half2 h = __float22half2_rn(f);
            vouth[(size_t)node * 16 + wd] = *(uint*)&h;
        }
    }
    float s = 0.0f, qq2 = 0.0f;
#pragma unroll
    for (int k = 0; k < 32; k++) {
        float vv = tile[(warp * 32 + k) * 33 + lane];
        s += vv;
        qq2 += vv * vv;
    }
    ps[warp * 32 + lane] = s;
    pq[warp * 32 + lane] = qq2;
    __syncthreads();
    if (tid < 32) {
        float ss = 0.0f, qs = 0.0f;
#pragma unroll
        for (int k = 0; k < 8; k++) {
            ss += ps[k * 32 + tid];
            qs += pq[k * 32 + tid];
        }
        atomicAdd(&stats[tid], ss);
        atomicAdd(&stats[32 + tid], qs);
    }
}

// ---------------------------------------------------------------------------
// Prep: stats -> (sc, sh); fold into next Wa if given.
// ---------------------------------------------------------------------------
__global__ void prep_kernel(const float* __restrict__ stats,
                            const float* __restrict__ gamma,
                            const float* __restrict__ beta,
                            const float* __restrict__ Wa, float* __restrict__ Wmod,
                            float* __restrict__ cvec, float* __restrict__ scsh,
                            float invN) {
    __shared__ float ssc[HDIM], ssh[HDIM];
    int tid = threadIdx.x;
    if (tid < HDIM) {
        float m = stats[tid] * invN;
        float var = stats[HDIM + tid] * invN - m * m;
        float sc = gamma[tid] * rsqrtf(var + BN_EPS);
        float sh = beta[tid] - m * sc;
        ssc[tid] = sc;
        ssh[tid] = sh;
        scsh[tid] = sc;
        scsh[HDIM + tid] = sh;
    }
    __syncthreads();
    if (Wa != nullptr) {
        if (tid < HDIM * HDIM) Wmod[tid] = ssc[tid >> 5] * Wa[tid];
        if (tid < HDIM) {
            float c = 0.0f;
#pragma unroll
            for (int i = 0; i < HDIM; i++) c += ssh[i] * Wa[i * HDIM + tid];
            cvec[tid] = c;
        }
    }
}

// ---------------------------------------------------------------------------
// Pool + head (fp16 final features; BN3 affine applied analytically).
// ---------------------------------------------------------------------------
__global__ void pool_kernel(const __half* __restrict__ v,
                            const float* __restrict__ scsh,
                            const float* __restrict__ Wf, const float* __restrict__ bf,
                            float* __restrict__ out, int n_graphs) {
    int g = (blockIdx.x * blockDim.x + threadIdx.x) >> 5;
    int lane = threadIdx.x & 31;
    if (g >= n_graphs) return;
    const __half* base = v + (size_t)g * NPG * HDIM;
    float s = 0.0f;
#pragma unroll 8
    for (int n = 0; n < NPG; n++) s += __half2float(base[n * HDIM + lane]);
    s = scsh[lane] * s + (float)NPG * scsh[HDIM + lane];
    float p0 = s * Wf[lane * 2 + 0];
    float p1 = s * Wf[lane * 2 + 1];
#pragma unroll
    for (int off = 16; off > 0; off >>= 1) {
        p0 += __shfl_xor_sync(0xFFFFFFFFu, p0, off);
        p1 += __shfl_xor_sync(0xFFFFFFFFu, p1, off);
    }
    if (lane == 0) {
        float l0 = p0 + bf[0];
        float l1 = p1 + bf[1];
        float m = fmaxf(l0, l1);
        float lse = m + logf(expf(l0 - m) + expf(l1 - m));
        out[g * 2 + 0] = l0 - lse;
        out[g * 2 + 1] = l1 - lse;
    }
}

// ---------------------------------------------------------------------------
// Launch. Kernel order: place(1), layer1(2), prep1(3), layer2(4) <- ncu.
// ---------------------------------------------------------------------------
extern "C" void kernel_launch(void* const* d_in, const int* in_sizes, int n_in,
                              void* d_out, int out_size) {
    const float* x   = (const float*)d_in[0];
    const int*   ei  = (const int*)d_in[1];
    const float* W1a = (const float*)d_in[3];
    const float* b1a = (const float*)d_in[4];
    const float* W1b = (const float*)d_in[5];
    const float* b1b = (const float*)d_in[6];
    const float* W2a = (const float*)d_in[7];
    const float* b2a = (const float*)d_in[8];
    const float* W2b = (const float*)d_in[9];
    const float* b2b = (const float*)d_in[10];
    const float* W3a = (const float*)d_in[11];
    const float* b3a = (const float*)d_in[12];
    const float* W3b = (const float*)d_in[13];
    const float* b3b = (const float*)d_in[14];
    const float* g1  = (const float*)d_in[15];
    const float* be1 = (const float*)d_in[16];
    const float* g2  = (const float*)d_in[17];
    const float* be2 = (const float*)d_in[18];
    const float* g3  = (const float*)d_in[19];
    const float* be3 = (const float*)d_in[20];
    const float* Wf  = (const float*)d_in[21];
    const float* bf  = (const float*)d_in[22];
    float* out = (float*)d_out;

    int n_nodes  = in_sizes[0] / NFEAT;
    int n_edges  = in_sizes[1] / 2;
    int n_graphs = n_nodes / NPG;
    const int* src = ei;
    const int* dst = ei + n_edges;

    float *stats, *Wmod, *cvec, *scsh;
    uint *bufA, *bufB;
    int *cnt, *colell;
    cudaGetSymbolAddress((void**)&bufA, g_bufA);
    cudaGetSymbolAddress((void**)&bufB, g_bufB);
    cudaGetSymbolAddress((void**)&stats, g_stats);
    cudaGetSymbolAddress((void**)&Wmod, g_Wmod);
    cudaGetSymbolAddress((void**)&cvec, g_cvec);
    cudaGetSymbolAddress((void**)&scsh, g_scsh);
    cudaGetSymbolAddress((void**)&cnt, g_cnt);
    cudaGetSymbolAddress((void**)&colell, g_colell);

    float invN = 1.0f / (float)n_nodes;
    int grid_e = (n_edges + 255) / 256;
    int grid_n = (n_nodes + 255) / 256;  // fused layers: 256 nodes per block

    // ---- ELL build (single pass) ----
    cudaMemsetAsync(cnt, 0, (size_t)n_nodes * sizeof(int), 0);
    cudaMemsetAsync(stats, 0, 6 * HDIM * sizeof(float), 0);
    place_kernel<<<grid_e, 256>>>(src, dst, cnt, colell, n_edges);       // k1

    // ---- Layer 1 (fused gather16 + MLP) ----
    layer1_kernel<<<grid_n, 256>>>((const ulonglong2*)x, cnt, colell,
                                   W1a, b1a, W1b, b1b, bufA,
                                   stats + 0, n_nodes);                  // k2
    prep_kernel<<<1, 1024>>>(stats + 0, g1, be1, W2a, Wmod, cvec, scsh, invN);  // k3

    // ---- Layer 2 (fused gather32h + MLP, BN1 folded) ----
    layer23_kernel<<<grid_n, 256>>>((const uint4*)bufA, cnt, colell,
                                    Wmod, cvec, b2a, W2b, b2b, bufB,
                                    stats + 64, n_nodes);                // k4 <- ncu
    prep_kernel<<<1, 1024>>>(stats + 64, g2, be2, W3a, Wmod, cvec, scsh, invN);

    // ---- Layer 3 (fused gather32h + MLP, BN2 folded) ----
    layer23_kernel<<<grid_n, 256>>>((const uint4*)bufB, cnt, colell,
                                    Wmod, cvec, b3a, W3b, b3b, bufA,
                                    stats + 128, n_nodes);
    prep_kernel<<<1, 1024>>>(stats + 128, g3, be3, nullptr, Wmod, cvec, scsh, invN);

    // ---- Pool + head ----
    int grid_p = (n_graphs * 32 + 255) / 256;
    pool_kernel<<<grid_p, 256>>>((const __half*)bufA, scsh, Wf, bf, out, n_graphs);
}

// round 14
// speedup vs baseline: 2.2838x; 2.2838x over previous
#include <cuda_runtime.h>
#include <cuda_fp16.h>
#include <math.h>

// ---------------------------------------------------------------------------
// GIN_37048387895934 — ELL gather (register-resident indices, smem-FREE
// gathers to preserve L1D) + packed-f32x2 MLP. fp16 storage, fp32 accumulate.
// Gather loops use warp-uniform trip count (dmax) -> convergent __shfl_sync.
// N=524288 nodes, E=8388608 edges, DIM=32, 8192 graphs x 64 nodes.
// ---------------------------------------------------------------------------

#define NFEAT 16
#define HDIM 32
#define NPG 64
#define BN_EPS 1e-5f
#define ELL_CAP 64  // Poisson(16): P(deg>64) ~ 3e-20 per node

typedef unsigned long long ull;
typedef unsigned int uint;

static constexpr int MAX_NODES = 8192 * 64;       // 524288

__device__ __align__(256) uint g_bufA[(size_t)MAX_NODES * HDIM / 2];  // fp16 rows
__device__ __align__(256) uint g_bufB[(size_t)MAX_NODES * HDIM / 2];  // fp16 rows
__device__ __align__(256) float g_agg[(size_t)MAX_NODES * HDIM];      // fp32 agg
__device__ int g_cnt[MAX_NODES];                                      // degree
__device__ __align__(16) int g_colell[(size_t)MAX_NODES * ELL_CAP];   // ELL columns
__device__ float g_stats[3 * 2 * HDIM];
__device__ __align__(16) float g_Wmod[HDIM * HDIM];
__device__ float g_cvec[HDIM];
__device__ float g_scsh[2 * HDIM];

// ---------------------------------------------------------------------------
// Packed math helpers.
// ---------------------------------------------------------------------------
__device__ __forceinline__ ull pack2(float x, float y) {
    ull r;
    asm("mov.b64 %0, {%1, %2};" : "=l"(r) : "f"(x), "f"(y));
    return r;
}
__device__ __forceinline__ void unpack2(ull v, float& x, float& y) {
    asm("mov.b64 {%0, %1}, %2;" : "=f"(x), "=f"(y) : "l"(v));
}
__device__ __forceinline__ ull fma2(ull a, ull b, ull c) {
    ull d;
    asm("fma.rn.f32x2 %0, %1, %2, %3;" : "=l"(d) : "l"(a), "l"(b), "l"(c));
    return d;
}
__device__ __forceinline__ ull add2(ull a, ull b) {
    ull d;
    asm("add.rn.f32x2 %0, %1, %2;" : "=l"(d) : "l"(a), "l"(b));
    return d;
}
// Accumulate a uint4 of 8 fp16 values into 4 packed-f32x2 accumulators.
__device__ __forceinline__ void hacc(uint4 u, ull& x0, ull& x1, ull& x2, ull& x3) {
    float2 f;
    f = __half22float2(*(__half2*)&u.x);
    x0 = add2(x0, pack2(f.x, f.y));
    f = __half22float2(*(__half2*)&u.y);
    x1 = add2(x1, pack2(f.x, f.y));
    f = __half22float2(*(__half2*)&u.z);
    x2 = add2(x2, pack2(f.x, f.y));
    f = __half22float2(*(__half2*)&u.w);
    x3 = add2(x3, pack2(f.x, f.y));
}
// Warp-max (groups of 4 share deg; offsets 4/8/16 reduce across the 8 groups).
__device__ __forceinline__ int warp_max_deg(int v) {
    v = max(v, __shfl_xor_sync(0xFFFFFFFFu, v, 4));
    v = max(v, __shfl_xor_sync(0xFFFFFFFFu, v, 8));
    v = max(v, __shfl_xor_sync(0xFFFFFFFFu, v, 16));
    return v;
}

// ---------------------------------------------------------------------------
// ELL build: single pass, no histogram/scan.
// ---------------------------------------------------------------------------
__global__ void place_kernel(const int* __restrict__ src, const int* __restrict__ dst,
                             int* __restrict__ cnt, int* __restrict__ colell,
                             int n_edges) {
    int e = blockIdx.x * blockDim.x + threadIdx.x;
    if (e < n_edges) {
        int d = __ldcs(&dst[e]);
        int p = atomicAdd(&cnt[d], 1);
        p = min(p, ELL_CAP - 1);  // statistically unreachable; avoids OOB
        colell[(size_t)d * ELL_CAP + p] = __ldcs(&src[e]);
    }
}

// ---------------------------------------------------------------------------
// Gather16 (layer 1, fp32 x): 8 nodes/warp, 4 lanes/node (row = 64B).
// smem-free (full L1D). Warp-uniform dmax loop; predicated feature loads.
// ---------------------------------------------------------------------------
__global__ __launch_bounds__(256) void gather16_kernel(
    const ulonglong2* __restrict__ x4, const int* __restrict__ cnt,
    const int* __restrict__ colell, ulonglong2* __restrict__ agg4, int n_nodes) {
    int lane = threadIdx.x & 31;
    int q = lane & 3;
    int w = (blockIdx.x * blockDim.x + threadIdx.x) >> 5;
    int node = w * 8 + (lane >> 2);
    int deg = min(__ldg(&cnt[node]), ELL_CAP);
    int dmax = warp_max_deg(deg);
    const int4* cb4 = (const int4*)(colell + (size_t)node * ELL_CAP);

    ulonglong2 self = __ldg(&x4[(size_t)node * 4 + q]);
    ull a0 = self.x, a1 = self.y;
    ull b0 = 0, b1 = 0;

    for (int b = 0; b < dmax; b += 16) {
        int4 i4 = __ldg(&cb4[(b >> 2) + q]);  // in-row for b<64; no guard needed
#pragma unroll
        for (int j = 0; j < 16; j += 4) {
            int o = j >> 2;
            int s0 = __shfl_sync(0xFFFFFFFFu, i4.x, o, 4);
            int s1 = __shfl_sync(0xFFFFFFFFu, i4.y, o, 4);
            int s2 = __shfl_sync(0xFFFFFFFFu, i4.z, o, 4);
            int s3 = __shfl_sync(0xFFFFFFFFu, i4.w, o, 4);
            if (b + j + 0 < deg) {
                ulonglong2 u = __ldg(&x4[(size_t)s0 * 4 + q]);
                a0 = add2(a0, u.x);
                a1 = add2(a1, u.y);
            }
            if (b + j + 1 < deg) {
                ulonglong2 u = __ldg(&x4[(size_t)s1 * 4 + q]);
                b0 = add2(b0, u.x);
                b1 = add2(b1, u.y);
            }
            if (b + j + 2 < deg) {
                ulonglong2 u = __ldg(&x4[(size_t)s2 * 4 + q]);
                a0 = add2(a0, u.x);
                a1 = add2(a1, u.y);
            }
            if (b + j + 3 < deg) {
                ulonglong2 u = __ldg(&x4[(size_t)s3 * 4 + q]);
                b0 = add2(b0, u.x);
                b1 = add2(b1, u.y);
            }
        }
    }
    ulonglong2 outv;
    outv.x = add2(a0, b0);
    outv.y = add2(a1, b1);
    agg4[(size_t)node * 4 + q] = outv;
}

// ---------------------------------------------------------------------------
// Gather32h (layers 2/3): fp16 rows in (64B, 4x16B chunks), fp32 accumulate,
// fp32 agg out. 8 nodes/warp, 4 lanes/node. smem-free. dmax loop.
// ---------------------------------------------------------------------------
__global__ __launch_bounds__(256) void gather32h_kernel(
    const uint4* __restrict__ vinh4, const int* __restrict__ cnt,
    const int* __restrict__ colell, ulonglong2* __restrict__ agg4, int n_nodes) {
    int lane = threadIdx.x & 31;
    int q = lane & 3;
    int w = (blockIdx.x * blockDim.x + threadIdx.x) >> 5;
    int node = w * 8 + (lane >> 2);
    int deg = min(__ldg(&cnt[node]), ELL_CAP);
    int dmax = warp_max_deg(deg);
    const int4* cb4 = (const int4*)(colell + (size_t)node * ELL_CAP);

    ull a0 = 0, a1 = 0, a2 = 0, a3 = 0;
    ull b0 = 0, b1 = 0, b2 = 0, b3 = 0;
    hacc(__ldg(&vinh4[(size_t)node * 4 + q]), a0, a1, a2, a3);  // self

    for (int b = 0; b < dmax; b += 16) {
        int4 i4 = __ldg(&cb4[(b >> 2) + q]);
#pragma unroll
        for (int j = 0; j < 16; j += 4) {
            int o = j >> 2;
            int s0 = __shfl_sync(0xFFFFFFFFu, i4.x, o, 4);
            int s1 = __shfl_sync(0xFFFFFFFFu, i4.y, o, 4);
            int s2 = __shfl_sync(0xFFFFFFFFu, i4.z, o, 4);
            int s3 = __shfl_sync(0xFFFFFFFFu, i4.w, o, 4);
            if (b + j + 0 < deg) hacc(__ldg(&vinh4[(size_t)s0 * 4 + q]), a0, a1, a2, a3);
            if (b + j + 1 < deg) hacc(__ldg(&vinh4[(size_t)s1 * 4 + q]), b0, b1, b2, b3);
            if (b + j + 2 < deg) hacc(__ldg(&vinh4[(size_t)s2 * 4 + q]), a0, a1, a2, a3);
            if (b + j + 3 < deg) hacc(__ldg(&vinh4[(size_t)s3 * 4 + q]), b0, b1, b2, b3);
        }
    }
    ulonglong2 o0, o1;
    o0.x = add2(a0, b0);
    o0.y = add2(a1, b1);
    o1.x = add2(a2, b2);
    o1.y = add2(a3, b3);
    agg4[(size_t)node * 8 + 2 * q] = o0;
    agg4[(size_t)node * 8 + 2 * q + 1] = o1;
}

// ---------------------------------------------------------------------------
// MLP16 (layer 1): fp32 16-dim agg in, fp16 32-dim out. Stats fused (fp32).
// ---------------------------------------------------------------------------
__global__ __launch_bounds__(256) void mlp16_kernel(
    const float* __restrict__ agg, const float* __restrict__ Wa,
    const float* __restrict__ ba, const float* __restrict__ Wb,
    const float* __restrict__ bb, uint* __restrict__ vouth,
    float* __restrict__ stats, int n_nodes) {
    __shared__ float tile[256 * 33];
    __shared__ __align__(16) ull sWa2[NFEAT * HDIM / 2];
    __shared__ __align__(16) ull sWb2[HDIM * HDIM / 2];
    __shared__ float sba[HDIM], sbb[HDIM];
    __shared__ float ps[8 * 32], pq[8 * 32];

    for (int i = threadIdx.x; i < NFEAT * HDIM / 2; i += 256)
        sWa2[i] = ((const ull*)Wa)[i];
    for (int i = threadIdx.x; i < HDIM * HDIM / 2; i += 256)
        sWb2[i] = ((const ull*)Wb)[i];
    if (threadIdx.x < HDIM) {
        sba[threadIdx.x] = ba[threadIdx.x];
        sbb[threadIdx.x] = bb[threadIdx.x];
    }
    __syncthreads();

    int warp = threadIdx.x >> 5;
    int lane = threadIdx.x & 31;
    int base = blockIdx.x * 256;
    int tid = threadIdx.x;

    size_t lim = (size_t)n_nodes * NFEAT;
#pragma unroll
    for (int off = 0; off < 16; off++) {
        int idx = off * 256 + tid;
        int row = idx >> 4, ch = idx & 15;
        size_t g = (size_t)base * NFEAT + idx;
        tile[row * 33 + ch] = (g < lim) ? __ldcs(&agg[g]) : 0.0f;
    }
    __syncthreads();

    bool valid = (base + tid) < n_nodes;
    float t[NFEAT];
#pragma unroll
    for (int i = 0; i < NFEAT; i++) t[i] = tile[tid * 33 + i];

    ull u2[16];
#pragma unroll
    for (int j = 0; j < 16; j++) u2[j] = pack2(sba[2 * j], sba[2 * j + 1]);
#pragma unroll
    for (int i = 0; i < NFEAT; i++) {
        ull tt = pack2(t[i], t[i]);
#pragma unroll
        for (int j = 0; j < 8; j++) {
            ulonglong2 w = *(const ulonglong2*)&sWa2[i * 16 + 2 * j];
            u2[2 * j] = fma2(tt, w.x, u2[2 * j]);
            u2[2 * j + 1] = fma2(tt, w.y, u2[2 * j + 1]);
        }
    }
    float uu[HDIM];
#pragma unroll
    for (int j = 0; j < 16; j++) {
        float a, b;
        unpack2(u2[j], a, b);
        uu[2 * j] = fmaxf(a, 0.0f);
        uu[2 * j + 1] = fmaxf(b, 0.0f);
    }
    ull v2[16];
#pragma unroll
    for (int j = 0; j < 16; j++) v2[j] = pack2(sbb[2 * j], sbb[2 * j + 1]);
#pragma unroll
    for (int i = 0; i < HDIM; i++) {
        ull tt = pack2(uu[i], uu[i]);
#pragma unroll
        for (int j = 0; j < 8; j++) {
            ulonglong2 w = *(const ulonglong2*)&sWb2[i * 16 + 2 * j];
            v2[2 * j] = fma2(tt, w.x, v2[2 * j]);
            v2[2 * j + 1] = fma2(tt, w.y, v2[2 * j + 1]);
        }
    }
#pragma unroll
    for (int j = 0; j < 16; j++) {
        float a, b;
        unpack2(v2[j], a, b);
        tile[tid * 33 + 2 * j] = valid ? fmaxf(a, 0.0f) : 0.0f;
        tile[tid * 33 + 2 * j + 1] = valid ? fmaxf(b, 0.0f) : 0.0f;
    }
    __syncthreads();

#pragma unroll
    for (int k = 0; k < 16; k++) {
        int rr = warp * 32 + 2 * k + (lane >> 4);
        int node = base + rr;
        int wd = lane & 15;
        if (node < n_nodes) {
            float2 f;
            f.x = tile[rr * 33 + 2 * wd];
            f.y = tile[rr * 33 + 2 * wd + 1];
            __half2 h = __float22half2_rn(f);
            vouth[(size_t)node * 16 + wd] = *(uint*)&h;
        }
    }
    float s = 0.0f, q = 0.0f;
#pragma unroll
    for (int k = 0; k < 32; k++) {
        float vv = tile[(warp * 32 + k) * 33 + lane];
        s += vv;
        q += vv * vv;
    }
    ps[warp * 32 + lane] = s;
    pq[warp * 32 + lane] = q;
    __syncthreads();
    if (tid < 32) {
        float ss = 0.0f, qq = 0.0f;
#pragma unroll
        for (int k = 0; k < 8; k++) {
            ss += ps[k * 32 + tid];
            qq += pq[k * 32 + tid];
        }
        atomicAdd(&stats[tid], ss);
        atomicAdd(&stats[32 + tid], qq);
    }
}

// ---------------------------------------------------------------------------
// MLP (layers 2/3): fp32 agg in, fp16 out; fp32 math; prev BN folded.
// ---------------------------------------------------------------------------
__global__ __launch_bounds__(256) void mlp_kernel(
    const float* __restrict__ agg, const int* __restrict__ cnt,
    const float* __restrict__ Wmod, const float* __restrict__ cvec,
    const float* __restrict__ ba, const float* __restrict__ Wb,
    const float* __restrict__ bb, uint* __restrict__ vouth,
    float* __restrict__ stats, int n_nodes) {
    __shared__ float tile[256 * 33];
    __shared__ __align__(16) ull sWa2[HDIM * HDIM / 2];
    __shared__ __align__(16) ull sWb2[HDIM * HDIM / 2];
    __shared__ float sba[HDIM], sbb[HDIM], scv[HDIM];
    __shared__ float ps[8 * 32], pq[8 * 32];

    for (int i = threadIdx.x; i < HDIM * HDIM / 2; i += 256) {
        sWa2[i] = ((const ull*)Wmod)[i];
        sWb2[i] = ((const ull*)Wb)[i];
    }
    if (threadIdx.x < HDIM) {
        sba[threadIdx.x] = ba[threadIdx.x];
        sbb[threadIdx.x] = bb[threadIdx.x];
        scv[threadIdx.x] = cvec[threadIdx.x];
    }
    __syncthreads();

    int warp = threadIdx.x >> 5;
    int lane = threadIdx.x & 31;
    int base = blockIdx.x * 256;
    int tid = threadIdx.x;

    for (int k = 0; k < 32; k++) {
        int row = warp * 32 + k;
        int node = base + row;
        tile[row * 33 + lane] =
            (node < n_nodes) ? __ldcs(&agg[(size_t)node * HDIM + lane]) : 0.0f;
    }
    __syncthreads();

    bool valid = (base + tid) < n_nodes;
    float degp1 = 1.0f;
    if (valid) degp1 = (float)cnt[base + tid] + 1.0f;
    ull u2[16];
#pragma unroll
    for (int j = 0; j < 16; j++)
        u2[j] = pack2(fmaf(degp1, scv[2 * j], sba[2 * j]),
                      fmaf(degp1, scv[2 * j + 1], sba[2 * j + 1]));
#pragma unroll
    for (int i = 0; i < HDIM; i++) {
        float ti = tile[tid * 33 + i];
        ull tt = pack2(ti, ti);
#pragma unroll
        for (int j = 0; j < 8; j++) {
            ulonglong2 w = *(const ulonglong2*)&sWa2[i * 16 + 2 * j];
            u2[2 * j] = fma2(tt, w.x, u2[2 * j]);
            u2[2 * j + 1] = fma2(tt, w.y, u2[2 * j + 1]);
        }
    }
    float uu[HDIM];
#pragma unroll
    for (int j = 0; j < 16; j++) {
        float a, b;
        unpack2(u2[j], a, b);
        uu[2 * j] = fmaxf(a, 0.0f);
        uu[2 * j + 1] = fmaxf(b, 0.0f);
    }
    ull v2[16];
#pragma unroll
    for (int j = 0; j < 16; j++) v2[j] = pack2(sbb[2 * j], sbb[2 * j + 1]);
#pragma unroll
    for (int i = 0; i < HDIM; i++) {
        ull tt = pack2(uu[i], uu[i]);
#pragma unroll
        for (int j = 0; j < 8; j++) {
            ulonglong2 w = *(const ulonglong2*)&sWb2[i * 16 + 2 * j];
            v2[2 * j] = fma2(tt, w.x, v2[2 * j]);
            v2[2 * j + 1] = fma2(tt, w.y, v2[2 * j + 1]);
        }
    }
#pragma unroll
    for (int j = 0; j < 16; j++) {
        float a, b;
        unpack2(v2[j], a, b);
        tile[tid * 33 + 2 * j] = valid ? fmaxf(a, 0.0f) : 0.0f;
        tile[tid * 33 + 2 * j + 1] = valid ? fmaxf(b, 0.0f) : 0.0f;
    }
    __syncthreads();

#pragma unroll
    for (int k = 0; k < 16; k++) {
        int rr = warp * 32 + 2 * k + (lane >> 4);
        int node = base + rr;
        int wd = lane & 15;
        if (node < n_nodes) {
            float2 f;
            f.x = tile[rr * 33 + 2 * wd];
            f.y = tile[rr * 33 + 2 * wd + 1];
            __half2 h = __float22half2_rn(f);
            vouth[(size_t)node * 16 + wd] = *(uint*)&h;
        }
    }
    float s = 0.0f, q = 0.0f;
#pragma unroll
    for (int k = 0; k < 32; k++) {
        float vv = tile[(warp * 32 + k) * 33 + lane];
        s += vv;
        q += vv * vv;
    }
    ps[warp * 32 + lane] = s;
    pq[warp * 32 + lane] = q;
    __syncthreads();
    if (tid < 32) {
        float ss = 0.0f, qq = 0.0f;
#pragma unroll
        for (int k = 0; k < 8; k++) {
            ss += ps[k * 32 + tid];
            qq += pq[k * 32 + tid];
        }
        atomicAdd(&stats[tid], ss);
        atomicAdd(&stats[32 + tid], qq);
    }
}

// ---------------------------------------------------------------------------
// Prep: stats -> (sc, sh); fold into next Wa if given.
// ---------------------------------------------------------------------------
__global__ void prep_kernel(const float* __restrict__ stats,
                            const float* __restrict__ gamma,
                            const float* __restrict__ beta,
                            const float* __restrict__ Wa, float* __restrict__ Wmod,
                            float* __restrict__ cvec, float* __restrict__ scsh,
                            float invN) {
    __shared__ float ssc[HDIM], ssh[HDIM];
    int tid = threadIdx.x;
    if (tid < HDIM) {
        float m = stats[tid] * invN;
        float var = stats[HDIM + tid] * invN - m * m;
        float sc = gamma[tid] * rsqrtf(var + BN_EPS);
        float sh = beta[tid] - m * sc;
        ssc[tid] = sc;
        ssh[tid] = sh;
        scsh[tid] = sc;
        scsh[HDIM + tid] = sh;
    }
    __syncthreads();
    if (Wa != nullptr) {
        if (tid < HDIM * HDIM) Wmod[tid] = ssc[tid >> 5] * Wa[tid];
        if (tid < HDIM) {
            float c = 0.0f;
#pragma unroll
            for (int i = 0; i < HDIM; i++) c += ssh[i] * Wa[i * HDIM + tid];
            cvec[tid] = c;
        }
    }
}

// ---------------------------------------------------------------------------
// Pool + head (fp16 final features; BN3 affine applied analytically).
// ---------------------------------------------------------------------------
__global__ void pool_kernel(const __half* __restrict__ v,
                            const float* __restrict__ scsh,
                            const float* __restrict__ Wf, const float* __restrict__ bf,
                            float* __restrict__ out, int n_graphs) {
    int g = (blockIdx.x * blockDim.x + threadIdx.x) >> 5;
    int lane = threadIdx.x & 31;
    if (g >= n_graphs) return;
    const __half* base = v + (size_t)g * NPG * HDIM;
    float s = 0.0f;
#pragma unroll 8
    for (int n = 0; n < NPG; n++) s += __half2float(base[n * HDIM + lane]);
    s = scsh[lane] * s + (float)NPG * scsh[HDIM + lane];
    float p0 = s * Wf[lane * 2 + 0];
    float p1 = s * Wf[lane * 2 + 1];
#pragma unroll
    for (int off = 16; off > 0; off >>= 1) {
        p0 += __shfl_xor_sync(0xFFFFFFFFu, p0, off);
        p1 += __shfl_xor_sync(0xFFFFFFFFu, p1, off);
    }
    if (lane == 0) {
        float l0 = p0 + bf[0];
        float l1 = p1 + bf[1];
        float m = fmaxf(l0, l1);
        float lse = m + logf(expf(l0 - m) + expf(l1 - m));
        out[g * 2 + 0] = l0 - lse;
        out[g * 2 + 1] = l1 - lse;
    }
}

// ---------------------------------------------------------------------------
// Launch. Kernel order: place(1), gather16(2), mlp16(3), gather32h(4) <- ncu.
// ---------------------------------------------------------------------------
extern "C" void kernel_launch(void* const* d_in, const int* in_sizes, int n_in,
                              void* d_out, int out_size) {
    const float* x   = (const float*)d_in[0];
    const int*   ei  = (const int*)d_in[1];
    const float* W1a = (const float*)d_in[3];
    const float* b1a = (const float*)d_in[4];
    const float* W1b = (const float*)d_in[5];
    const float* b1b = (const float*)d_in[6];
    const float* W2a = (const float*)d_in[7];
    const float* b2a = (const float*)d_in[8];
    const float* W2b = (const float*)d_in[9];
    const float* b2b = (const float*)d_in[10];
    const float* W3a = (const float*)d_in[11];
    const float* b3a = (const float*)d_in[12];
    const float* W3b = (const float*)d_in[13];
    const float* b3b = (const float*)d_in[14];
    const float* g1  = (const float*)d_in[15];
    const float* be1 = (const float*)d_in[16];
    const float* g2  = (const float*)d_in[17];
    const float* be2 = (const float*)d_in[18];
    const float* g3  = (const float*)d_in[19];
    const float* be3 = (const float*)d_in[20];
    const float* Wf  = (const float*)d_in[21];
    const float* bf  = (const float*)d_in[22];
    float* out = (float*)d_out;

    int n_nodes  = in_sizes[0] / NFEAT;
    int n_edges  = in_sizes[1] / 2;
    int n_graphs = n_nodes / NPG;
    const int* src = ei;
    const int* dst = ei + n_edges;

    float *agg, *stats, *Wmod, *cvec, *scsh;
    uint *bufA, *bufB;
    int *cnt, *colell;
    cudaGetSymbolAddress((void**)&bufA, g_bufA);
    cudaGetSymbolAddress((void**)&bufB, g_bufB);
    cudaGetSymbolAddress((void**)&agg, g_agg);
    cudaGetSymbolAddress((void**)&stats, g_stats);
    cudaGetSymbolAddress((void**)&Wmod, g_Wmod);
    cudaGetSymbolAddress((void**)&cvec, g_cvec);
    cudaGetSymbolAddress((void**)&scsh, g_scsh);
    cudaGetSymbolAddress((void**)&cnt, g_cnt);
    cudaGetSymbolAddress((void**)&colell, g_colell);

    float invN = 1.0f / (float)n_nodes;
    int grid_e = (n_edges + 255) / 256;
    int grid_n = (n_nodes + 255) / 256;       // mlp: 256 nodes per block
    int grid_g = (n_nodes * 4 + 255) / 256;   // gathers: 4 threads/node

    // ---- ELL build (single pass) ----
    cudaMemsetAsync(cnt, 0, (size_t)n_nodes * sizeof(int), 0);
    cudaMemsetAsync(stats, 0, 6 * HDIM * sizeof(float), 0);
    place_kernel<<<grid_e, 256>>>(src, dst, cnt, colell, n_edges);   // k1

    // ---- Layer 1 (fp32 16-dim gather on raw x; W1a folded into MLP) ----
    gather16_kernel<<<grid_g, 256>>>((const ulonglong2*)x, cnt, colell,
                                     (ulonglong2*)agg, n_nodes);     // k2
    mlp16_kernel<<<grid_n, 256>>>(agg, W1a, b1a, W1b, b1b, bufA,
                                  stats + 0, n_nodes);               // k3

    // ---- Layer 2 (fp16 gather, fp32 accumulate) ----
    gather32h_kernel<<<grid_g, 256>>>((const uint4*)bufA, cnt, colell,
                                      (ulonglong2*)agg, n_nodes);    // k4 <- ncu
    prep_kernel<<<1, 1024>>>(stats + 0, g1, be1, W2a, Wmod, cvec, scsh, invN);
    mlp_kernel<<<grid_n, 256>>>(agg, cnt, Wmod, cvec, b2a,
                                W2b, b2b, bufB, stats + 64, n_nodes);
    prep_kernel<<<1, 1024>>>(stats + 64, g2, be2, W3a, Wmod, cvec, scsh, invN);

    // ---- Layer 3 (fp16 gather, fp32 accumulate) ----
    gather32h_kernel<<<grid_g, 256>>>((const uint4*)bufB, cnt, colell,
                                      (ulonglong2*)agg, n_nodes);
    mlp_kernel<<<grid_n, 256>>>(agg, cnt, Wmod, cvec, b3a,
                                W3b, b3b, bufA, stats + 128, n_nodes);
    prep_kernel<<<1, 1024>>>(stats + 128, g3, be3, nullptr, Wmod, cvec, scsh, invN);

    // ---- Pool + head ----
    int grid_p = (n_graphs * 32 + 255) / 256;
    pool_kernel<<<grid_p, 256>>>((const __half*)bufA, scsh, Wf, bf, out, n_graphs);
}

// round 15
// speedup vs baseline: 2.2915x; 1.0034x over previous
#include <cuda_runtime.h>
#include <cuda_fp16.h>
#include <math.h>

// ---------------------------------------------------------------------------
// GIN_37048387895934 — ELL gather (smem-free, warp-uniform) + f32x2 MLP with
// BN-fold computed in-kernel (no prep launches). fp16 storage, fp32 accum.
// N=524288 nodes, E=8388608 edges, DIM=32, 8192 graphs x 64 nodes.
// ---------------------------------------------------------------------------

#define NFEAT 16
#define HDIM 32
#define NPG 64
#define BN_EPS 1e-5f
#define ELL_CAP 64

typedef unsigned long long ull;
typedef unsigned int uint;

static constexpr int MAX_NODES = 8192 * 64;

__device__ __align__(256) uint g_bufA[(size_t)MAX_NODES * HDIM / 2];
__device__ __align__(256) uint g_bufB[(size_t)MAX_NODES * HDIM / 2];
__device__ __align__(256) float g_agg[(size_t)MAX_NODES * HDIM];
__device__ int g_cnt[MAX_NODES];
__device__ __align__(16) int g_colell[(size_t)MAX_NODES * ELL_CAP];
__device__ float g_stats[3 * 2 * HDIM];

// ---------------------------------------------------------------------------
// Packed math helpers.
// ---------------------------------------------------------------------------
__device__ __forceinline__ ull pack2(float x, float y) {
    ull r;
    asm("mov.b64 %0, {%1, %2};" : "=l"(r) : "f"(x), "f"(y));
    return r;
}
__device__ __forceinline__ void unpack2(ull v, float& x, float& y) {
    asm("mov.b64 {%0, %1}, %2;" : "=f"(x), "=f"(y) : "l"(v));
}
__device__ __forceinline__ ull fma2(ull a, ull b, ull c) {
    ull d;
    asm("fma.rn.f32x2 %0, %1, %2, %3;" : "=l"(d) : "l"(a), "l"(b), "l"(c));
    return d;
}
__device__ __forceinline__ ull add2(ull a, ull b) {
    ull d;
    asm("add.rn.f32x2 %0, %1, %2;" : "=l"(d) : "l"(a), "l"(b));
    return d;
}
__device__ __forceinline__ void hacc(uint4 u, ull& x0, ull& x1, ull& x2, ull& x3) {
    float2 f;
    f = __half22float2(*(__half2*)&u.x);
    x0 = add2(x0, pack2(f.x, f.y));
    f = __half22float2(*(__half2*)&u.y);
    x1 = add2(x1, pack2(f.x, f.y));
    f = __half22float2(*(__half2*)&u.z);
    x2 = add2(x2, pack2(f.x, f.y));
    f = __half22float2(*(__half2*)&u.w);
    x3 = add2(x3, pack2(f.x, f.y));
}
__device__ __forceinline__ int warp_max_deg(int v) {
    v = max(v, __shfl_xor_sync(0xFFFFFFFFu, v, 4));
    v = max(v, __shfl_xor_sync(0xFFFFFFFFu, v, 8));
    v = max(v, __shfl_xor_sync(0xFFFFFFFFu, v, 16));
    return v;
}

// ---------------------------------------------------------------------------
// ELL build: single pass, 4 edges per thread (int4 loads).
// ---------------------------------------------------------------------------
__global__ void place_kernel(const int4* __restrict__ src4,
                             const int4* __restrict__ dst4,
                             int* __restrict__ cnt, int* __restrict__ colell,
                             int n_edges4) {
    int e = blockIdx.x * blockDim.x + threadIdx.x;
    if (e < n_edges4) {
        int4 s = __ldcs(&src4[e]);
        int4 d = __ldcs(&dst4[e]);
        int p;
        p = min(atomicAdd(&cnt[d.x], 1), ELL_CAP - 1);
        __stcs(&colell[(size_t)d.x * ELL_CAP + p], s.x);
        p = min(atomicAdd(&cnt[d.y], 1), ELL_CAP - 1);
        __stcs(&colell[(size_t)d.y * ELL_CAP + p], s.y);
        p = min(atomicAdd(&cnt[d.z], 1), ELL_CAP - 1);
        __stcs(&colell[(size_t)d.z * ELL_CAP + p], s.z);
        p = min(atomicAdd(&cnt[d.w], 1), ELL_CAP - 1);
        __stcs(&colell[(size_t)d.w * ELL_CAP + p], s.w);
    }
}

// ---------------------------------------------------------------------------
// Gather16 (layer 1, fp32 x): 8 nodes/warp, 4 lanes/node. smem-free. dmax loop.
// ---------------------------------------------------------------------------
__global__ __launch_bounds__(256) void gather16_kernel(
    const ulonglong2* __restrict__ x4, const int* __restrict__ cnt,
    const int* __restrict__ colell, ulonglong2* __restrict__ agg4, int n_nodes) {
    int lane = threadIdx.x & 31;
    int q = lane & 3;
    int w = (blockIdx.x * blockDim.x + threadIdx.x) >> 5;
    int node = w * 8 + (lane >> 2);
    int deg = min(__ldg(&cnt[node]), ELL_CAP);
    int dmax = warp_max_deg(deg);
    const int4* cb4 = (const int4*)(colell + (size_t)node * ELL_CAP);

    ulonglong2 self = __ldg(&x4[(size_t)node * 4 + q]);
    ull a0 = self.x, a1 = self.y;
    ull b0 = 0, b1 = 0;

    for (int b = 0; b < dmax; b += 16) {
        int4 i4 = __ldg(&cb4[(b >> 2) + q]);
#pragma unroll
        for (int j = 0; j < 16; j += 4) {
            int o = j >> 2;
            int s0 = __shfl_sync(0xFFFFFFFFu, i4.x, o, 4);
            int s1 = __shfl_sync(0xFFFFFFFFu, i4.y, o, 4);
            int s2 = __shfl_sync(0xFFFFFFFFu, i4.z, o, 4);
            int s3 = __shfl_sync(0xFFFFFFFFu, i4.w, o, 4);
            if (b + j + 0 < deg) {
                ulonglong2 u = __ldg(&x4[(size_t)s0 * 4 + q]);
                a0 = add2(a0, u.x);
                a1 = add2(a1, u.y);
            }
            if (b + j + 1 < deg) {
                ulonglong2 u = __ldg(&x4[(size_t)s1 * 4 + q]);
                b0 = add2(b0, u.x);
                b1 = add2(b1, u.y);
            }
            if (b + j + 2 < deg) {
                ulonglong2 u = __ldg(&x4[(size_t)s2 * 4 + q]);
                a0 = add2(a0, u.x);
                a1 = add2(a1, u.y);
            }
            if (b + j + 3 < deg) {
                ulonglong2 u = __ldg(&x4[(size_t)s3 * 4 + q]);
                b0 = add2(b0, u.x);
                b1 = add2(b1, u.y);
            }
        }
    }
    ulonglong2 outv;
    outv.x = add2(a0, b0);
    outv.y = add2(a1, b1);
    agg4[(size_t)node * 4 + q] = outv;
}

// ---------------------------------------------------------------------------
// Gather32h (layers 2/3): fp16 rows in, fp32 accumulate, fp32 agg out.
// 8 nodes/warp, 4 lanes/node. smem-free. dmax loop.
// ---------------------------------------------------------------------------
__global__ __launch_bounds__(256) void gather32h_kernel(
    const uint4* __restrict__ vinh4, const int* __restrict__ cnt,
    const int* __restrict__ colell, ulonglong2* __restrict__ agg4, int n_nodes) {
    int lane = threadIdx.x & 31;
    int q = lane & 3;
    int w = (blockIdx.x * blockDim.x + threadIdx.x) >> 5;
    int node = w * 8 + (lane >> 2);
    int deg = min(__ldg(&cnt[node]), ELL_CAP);
    int dmax = warp_max_deg(deg);
    const int4* cb4 = (const int4*)(colell + (size_t)node * ELL_CAP);

    ull a0 = 0, a1 = 0, a2 = 0, a3 = 0;
    ull b0 = 0, b1 = 0, b2 = 0, b3 = 0;
    hacc(__ldg(&vinh4[(size_t)node * 4 + q]), a0, a1, a2, a3);  // self

    for (int b = 0; b < dmax; b += 16) {
        int4 i4 = __ldg(&cb4[(b >> 2) + q]);
#pragma unroll
        for (int j = 0; j < 16; j += 4) {
            int o = j >> 2;
            int s0 = __shfl_sync(0xFFFFFFFFu, i4.x, o, 4);
            int s1 = __shfl_sync(0xFFFFFFFFu, i4.y, o, 4);
            int s2 = __shfl_sync(0xFFFFFFFFu, i4.z, o, 4);
            int s3 = __shfl_sync(0xFFFFFFFFu, i4.w, o, 4);
            if (b + j + 0 < deg) hacc(__ldg(&vinh4[(size_t)s0 * 4 + q]), a0, a1, a2, a3);
            if (b + j + 1 < deg) hacc(__ldg(&vinh4[(size_t)s1 * 4 + q]), b0, b1, b2, b3);
            if (b + j + 2 < deg) hacc(__ldg(&vinh4[(size_t)s2 * 4 + q]), a0, a1, a2, a3);
            if (b + j + 3 < deg) hacc(__ldg(&vinh4[(size_t)s3 * 4 + q]), b0, b1, b2, b3);
        }
    }
    ulonglong2 o0, o1;
    o0.x = add2(a0, b0);
    o0.y = add2(a1, b1);
    o1.x = add2(a2, b2);
    o1.y = add2(a3, b3);
    agg4[(size_t)node * 8 + 2 * q] = o0;
    agg4[(size_t)node * 8 + 2 * q + 1] = o1;
}

// ---------------------------------------------------------------------------
// MLP16 (layer 1): fp32 16-dim agg in, fp16 32-dim out. Stats fused.
// ---------------------------------------------------------------------------
__global__ __launch_bounds__(256) void mlp16_kernel(
    const float* __restrict__ agg, const float* __restrict__ Wa,
    const float* __restrict__ ba, const float* __restrict__ Wb,
    const float* __restrict__ bb, uint* __restrict__ vouth,
    float* __restrict__ stats, int n_nodes) {
    __shared__ float tile[256 * 33];
    __shared__ __align__(16) ull sWa2[NFEAT * HDIM / 2];
    __shared__ __align__(16) ull sWb2[HDIM * HDIM / 2];
    __shared__ float sba[HDIM], sbb[HDIM];
    __shared__ float ps[8 * 32], pq[8 * 32];

    for (int i = threadIdx.x; i < NFEAT * HDIM / 2; i += 256)
        sWa2[i] = ((const ull*)Wa)[i];
    for (int i = threadIdx.x; i < HDIM * HDIM / 2; i += 256)
        sWb2[i] = ((const ull*)Wb)[i];
    if (threadIdx.x < HDIM) {
        sba[threadIdx.x] = ba[threadIdx.x];
        sbb[threadIdx.x] = bb[threadIdx.x];
    }
    __syncthreads();

    int warp = threadIdx.x >> 5;
    int lane = threadIdx.x & 31;
    int base = blockIdx.x * 256;
    int tid = threadIdx.x;

    size_t lim = (size_t)n_nodes * NFEAT;
#pragma unroll
    for (int off = 0; off < 16; off++) {
        int idx = off * 256 + tid;
        int row = idx >> 4, ch = idx & 15;
        size_t g = (size_t)base * NFEAT + idx;
        tile[row * 33 + ch] = (g < lim) ? __ldcs(&agg[g]) : 0.0f;
    }
    __syncthreads();

    bool valid = (base + tid) < n_nodes;
    float t[NFEAT];
#pragma unroll
    for (int i = 0; i < NFEAT; i++) t[i] = tile[tid * 33 + i];

    ull u2[16];
#pragma unroll
    for (int j = 0; j < 16; j++) u2[j] = pack2(sba[2 * j], sba[2 * j + 1]);
#pragma unroll
    for (int i = 0; i < NFEAT; i++) {
        ull tt = pack2(t[i], t[i]);
#pragma unroll
        for (int j = 0; j < 8; j++) {
            ulonglong2 w = *(const ulonglong2*)&sWa2[i * 16 + 2 * j];
            u2[2 * j] = fma2(tt, w.x, u2[2 * j]);
            u2[2 * j + 1] = fma2(tt, w.y, u2[2 * j + 1]);
        }
    }
    float uu[HDIM];
#pragma unroll
    for (int j = 0; j < 16; j++) {
        float a, b;
        unpack2(u2[j], a, b);
        uu[2 * j] = fmaxf(a, 0.0f);
        uu[2 * j + 1] = fmaxf(b, 0.0f);
    }
    ull v2[16];
#pragma unroll
    for (int j = 0; j < 16; j++) v2[j] = pack2(sbb[2 * j], sbb[2 * j + 1]);
#pragma unroll
    for (int i = 0; i < HDIM; i++) {
        ull tt = pack2(uu[i], uu[i]);
#pragma unroll
        for (int j = 0; j < 8; j++) {
            ulonglong2 w = *(const ulonglong2*)&sWb2[i * 16 + 2 * j];
            v2[2 * j] = fma2(tt, w.x, v2[2 * j]);
            v2[2 * j + 1] = fma2(tt, w.y, v2[2 * j + 1]);
        }
    }
#pragma unroll
    for (int j = 0; j < 16; j++) {
        float a, b;
        unpack2(v2[j], a, b);
        tile[tid * 33 + 2 * j] = valid ? fmaxf(a, 0.0f) : 0.0f;
        tile[tid * 33 + 2 * j + 1] = valid ? fmaxf(b, 0.0f) : 0.0f;
    }
    __syncthreads();

#pragma unroll
    for (int k = 0; k < 16; k++) {
        int rr = warp * 32 + 2 * k + (lane >> 4);
        int node = base + rr;
        int wd = lane & 15;
        if (node < n_nodes) {
            float2 f;
            f.x = tile[rr * 33 + 2 * wd];
            f.y = tile[rr * 33 + 2 * wd + 1];
            __half2 h = __float22half2_rn(f);
            vouth[(size_t)node * 16 + wd] = *(uint*)&h;
        }
    }
    float s = 0.0f, q = 0.0f;
#pragma unroll
    for (int k = 0; k < 32; k++) {
        float vv = tile[(warp * 32 + k) * 33 + lane];
        s += vv;
        q += vv * vv;
    }
    ps[warp * 32 + lane] = s;
    pq[warp * 32 + lane] = q;
    __syncthreads();
    if (tid < 32) {
        float ss = 0.0f, qq = 0.0f;
#pragma unroll
        for (int k = 0; k < 8; k++) {
            ss += ps[k * 32 + tid];
            qq += pq[k * 32 + tid];
        }
        atomicAdd(&stats[tid], ss);
        atomicAdd(&stats[32 + tid], qq);
    }
}

// ---------------------------------------------------------------------------
// MLP (layers 2/3): fp32 agg in, fp16 out. PREVIOUS layer's BN is folded
// IN-KERNEL: (sc,sh) from pstats/pgamma/pbeta; Wa scaled while staging;
// cvec computed per block. Eliminates prep_kernel launches.
// ---------------------------------------------------------------------------
__global__ __launch_bounds__(256) void mlp_kernel(
    const float* __restrict__ agg, const int* __restrict__ cnt,
    const float* __restrict__ pstats, const float* __restrict__ pgamma,
    const float* __restrict__ pbeta, const float* __restrict__ Wa,
    const float* __restrict__ ba, const float* __restrict__ Wb,
    const float* __restrict__ bb, uint* __restrict__ vouth,
    float* __restrict__ stats, float invN, int n_nodes) {
    __shared__ float tile[256 * 33];
    __shared__ __align__(16) ull sWa2[HDIM * HDIM / 2];
    __shared__ __align__(16) ull sWb2[HDIM * HDIM / 2];
    __shared__ float sba[HDIM], sbb[HDIM], scv[HDIM];
    __shared__ float ssc[HDIM], ssh[HDIM];
    __shared__ float ps[8 * 32], pq[8 * 32];

    int tid = threadIdx.x;
    // BN constants of previous layer
    if (tid < HDIM) {
        float m = pstats[tid] * invN;
        float var = pstats[HDIM + tid] * invN - m * m;
        float sc = pgamma[tid] * rsqrtf(var + BN_EPS);
        ssc[tid] = sc;
        ssh[tid] = pbeta[tid] - m * sc;
        sba[tid] = ba[tid];
        sbb[tid] = bb[tid];
    }
    __syncthreads();
    // Stage Wmod = diag(sc) @ Wa (pair p covers elements 2p,2p+1; row = p>>4)
    for (int p = tid; p < HDIM * HDIM / 2; p += 256) {
        float sc = ssc[p >> 4];
        sWa2[p] = pack2(sc * Wa[2 * p], sc * Wa[2 * p + 1]);
        sWb2[p] = ((const ull*)Wb)[p];
    }
    if (tid < HDIM) {
        float c = 0.0f;
#pragma unroll
        for (int i = 0; i < HDIM; i++) c = fmaf(ssh[i], __ldg(&Wa[i * HDIM + tid]), c);
        scv[tid] = c;
    }
    __syncthreads();

    int warp = tid >> 5;
    int lane = tid & 31;
    int base = blockIdx.x * 256;

    for (int k = 0; k < 32; k++) {
        int row = warp * 32 + k;
        int node = base + row;
        tile[row * 33 + lane] =
            (node < n_nodes) ? __ldcs(&agg[(size_t)node * HDIM + lane]) : 0.0f;
    }
    __syncthreads();

    bool valid = (base + tid) < n_nodes;
    float degp1 = 1.0f;
    if (valid) degp1 = (float)cnt[base + tid] + 1.0f;
    ull u2[16];
#pragma unroll
    for (int j = 0; j < 16; j++)
        u2[j] = pack2(fmaf(degp1, scv[2 * j], sba[2 * j]),
                      fmaf(degp1, scv[2 * j + 1], sba[2 * j + 1]));
#pragma unroll
    for (int i = 0; i < HDIM; i++) {
        float ti = tile[tid * 33 + i];
        ull tt = pack2(ti, ti);
#pragma unroll
        for (int j = 0; j < 8; j++) {
            ulonglong2 w = *(const ulonglong2*)&sWa2[i * 16 + 2 * j];
            u2[2 * j] = fma2(tt, w.x, u2[2 * j]);
            u2[2 * j + 1] = fma2(tt, w.y, u2[2 * j + 1]);
        }
    }
    float uu[HDIM];
#pragma unroll
    for (int j = 0; j < 16; j++) {
        float a, b;
        unpack2(u2[j], a, b);
        uu[2 * j] = fmaxf(a, 0.0f);
        uu[2 * j + 1] = fmaxf(b, 0.0f);
    }
    ull v2[16];
#pragma unroll
    for (int j = 0; j < 16; j++) v2[j] = pack2(sbb[2 * j], sbb[2 * j + 1]);
#pragma unroll
    for (int i = 0; i < HDIM; i++) {
        ull tt = pack2(uu[i], uu[i]);
#pragma unroll
        for (int j = 0; j < 8; j++) {
            ulonglong2 w = *(const ulonglong2*)&sWb2[i * 16 + 2 * j];
            v2[2 * j] = fma2(tt, w.x, v2[2 * j]);
            v2[2 * j + 1] = fma2(tt, w.y, v2[2 * j + 1]);
        }
    }
#pragma unroll
    for (int j = 0; j < 16; j++) {
        float a, b;
        unpack2(v2[j], a, b);
        tile[tid * 33 + 2 * j] = valid ? fmaxf(a, 0.0f) : 0.0f;
        tile[tid * 33 + 2 * j + 1] = valid ? fmaxf(b, 0.0f) : 0.0f;
    }
    __syncthreads();

#pragma unroll
    for (int k = 0; k < 16; k++) {
        int rr = warp * 32 + 2 * k + (lane >> 4);
        int node = base + rr;
        int wd = lane & 15;
        if (node < n_nodes) {
            float2 f;
            f.x = tile[rr * 33 + 2 * wd];
            f.y = tile[rr * 33 + 2 * wd + 1];
            __half2 h = __float22half2_rn(f);
            vouth[(size_t)node * 16 + wd] = *(uint*)&h;
        }
    }
    float s = 0.0f, q = 0.0f;
#pragma unroll
    for (int k = 0; k < 32; k++) {
        float vv = tile[(warp * 32 + k) * 33 + lane];
        s += vv;
        q += vv * vv;
    }
    ps[warp * 32 + lane] = s;
    pq[warp * 32 + lane] = q;
    __syncthreads();
    if (tid < 32) {
        float ss = 0.0f, qq = 0.0f;
#pragma unroll
        for (int k = 0; k < 8; k++) {
            ss += ps[k * 32 + tid];
            qq += pq[k * 32 + tid];
        }
        atomicAdd(&stats[tid], ss);
        atomicAdd(&stats[32 + tid], qq);
    }
}

// ---------------------------------------------------------------------------
// Pool + head: BN3 (sc,sh) computed in-kernel from stats3; applied on pooled
// sums analytically; 32->2 linear + log_softmax. Warp per graph.
// ---------------------------------------------------------------------------
__global__ void pool_kernel(const __half* __restrict__ v,
                            const float* __restrict__ pstats,
                            const float* __restrict__ pgamma,
                            const float* __restrict__ pbeta,
                            const float* __restrict__ Wf, const float* __restrict__ bf,
                            float* __restrict__ out, float invN, int n_graphs) {
    __shared__ float ssc[HDIM], ssh[HDIM];
    if (threadIdx.x < HDIM) {
        float m = pstats[threadIdx.x] * invN;
        float var = pstats[HDIM + threadIdx.x] * invN - m * m;
        float sc = pgamma[threadIdx.x] * rsqrtf(var + BN_EPS);
        ssc[threadIdx.x] = sc;
        ssh[threadIdx.x] = pbeta[threadIdx.x] - m * sc;
    }
    __syncthreads();
    int g = (blockIdx.x * blockDim.x + threadIdx.x) >> 5;
    int lane = threadIdx.x & 31;
    if (g >= n_graphs) return;
    const __half* base = v + (size_t)g * NPG * HDIM;
    float s = 0.0f;
#pragma unroll 8
    for (int n = 0; n < NPG; n++) s += __half2float(base[n * HDIM + lane]);
    s = ssc[lane] * s + (float)NPG * ssh[lane];
    float p0 = s * Wf[lane * 2 + 0];
    float p1 = s * Wf[lane * 2 + 1];
#pragma unroll
    for (int off = 16; off > 0; off >>= 1) {
        p0 += __shfl_xor_sync(0xFFFFFFFFu, p0, off);
        p1 += __shfl_xor_sync(0xFFFFFFFFu, p1, off);
    }
    if (lane == 0) {
        float l0 = p0 + bf[0];
        float l1 = p1 + bf[1];
        float m = fmaxf(l0, l1);
        float lse = m + logf(expf(l0 - m) + expf(l1 - m));
        out[g * 2 + 0] = l0 - lse;
        out[g * 2 + 1] = l1 - lse;
    }
}

// ---------------------------------------------------------------------------
// Launch. Kernel order: place(1), gather16(2), mlp16(3), gather32h(4) <- ncu.
// ---------------------------------------------------------------------------
extern "C" void kernel_launch(void* const* d_in, const int* in_sizes, int n_in,
                              void* d_out, int out_size) {
    const float* x   = (const float*)d_in[0];
    const int*   ei  = (const int*)d_in[1];
    const float* W1a = (const float*)d_in[3];
    const float* b1a = (const float*)d_in[4];
    const float* W1b = (const float*)d_in[5];
    const float* b1b = (const float*)d_in[6];
    const float* W2a = (const float*)d_in[7];
    const float* b2a = (const float*)d_in[8];
    const float* W2b = (const float*)d_in[9];
    const float* b2b = (const float*)d_in[10];
    const float* W3a = (const float*)d_in[11];
    const float* b3a = (const float*)d_in[12];
    const float* W3b = (const float*)d_in[13];
    const float* b3b = (const float*)d_in[14];
    const float* g1  = (const float*)d_in[15];
    const float* be1 = (const float*)d_in[16];
    const float* g2  = (const float*)d_in[17];
    const float* be2 = (const float*)d_in[18];
    const float* g3  = (const float*)d_in[19];
    const float* be3 = (const float*)d_in[20];
    const float* Wf  = (const float*)d_in[21];
    const float* bf  = (const float*)d_in[22];
    float* out = (float*)d_out;

    int n_nodes  = in_sizes[0] / NFEAT;
    int n_edges  = in_sizes[1] / 2;
    int n_graphs = n_nodes / NPG;
    const int* src = ei;
    const int* dst = ei + n_edges;

    float *agg, *stats;
    uint *bufA, *bufB;
    int *cnt, *colell;
    cudaGetSymbolAddress((void**)&bufA, g_bufA);
    cudaGetSymbolAddress((void**)&bufB, g_bufB);
    cudaGetSymbolAddress((void**)&agg, g_agg);
    cudaGetSymbolAddress((void**)&stats, g_stats);
    cudaGetSymbolAddress((void**)&cnt, g_cnt);
    cudaGetSymbolAddress((void**)&colell, g_colell);

    float invN = 1.0f / (float)n_nodes;
    int n_edges4 = n_edges / 4;           // E = 8388608, divisible by 4
    int grid_e4 = (n_edges4 + 255) / 256;
    int grid_n = (n_nodes + 255) / 256;
    int grid_g = (n_nodes * 4 + 255) / 256;

    // ---- ELL build (single pass, 4 edges/thread) ----
    cudaMemsetAsync(cnt, 0, (size_t)n_nodes * sizeof(int), 0);
    cudaMemsetAsync(stats, 0, 6 * HDIM * sizeof(float), 0);
    place_kernel<<<grid_e4, 256>>>((const int4*)src, (const int4*)dst,
                                   cnt, colell, n_edges4);           // k1

    // ---- Layer 1 ----
    gather16_kernel<<<grid_g, 256>>>((const ulonglong2*)x, cnt, colell,
                                     (ulonglong2*)agg, n_nodes);     // k2
    mlp16_kernel<<<grid_n, 256>>>(agg, W1a, b1a, W1b, b1b, bufA,
                                  stats + 0, n_nodes);               // k3

    // ---- Layer 2 (BN1 folded in-kernel) ----
    gather32h_kernel<<<grid_g, 256>>>((const uint4*)bufA, cnt, colell,
                                      (ulonglong2*)agg, n_nodes);    // k4 <- ncu
    mlp_kernel<<<grid_n, 256>>>(agg, cnt, stats + 0, g1, be1, W2a, b2a,
                                W2b, b2b, bufB, stats + 64, invN, n_nodes);

    // ---- Layer 3 (BN2 folded in-kernel) ----
    gather32h_kernel<<<grid_g, 256>>>((const uint4*)bufB, cnt, colell,
                                      (ulonglong2*)agg, n_nodes);
    mlp_kernel<<<grid_n, 256>>>(agg, cnt, stats + 64, g2, be2, W3a, b3a,
                                W3b, b3b, bufA, stats + 128, invN, n_nodes);

    // ---- Pool + head (BN3 folded in-kernel) ----
    int grid_p = (n_graphs * 32 + 255) / 256;
    pool_kernel<<<grid_p, 256>>>((const __half*)bufA, stats + 128, g3, be3,
                                 Wf, bf, out, invN, n_graphs);
}

// round 16
// speedup vs baseline: 2.3799x; 1.0386x over previous
#include <cuda_runtime.h>
#include <cuda_fp16.h>
#include <math.h>

// ---------------------------------------------------------------------------
// GIN_37048387895934 — ELL gather (smem-free, warp-uniform) + f32x2 MLP with
// in-kernel BN fold; layer-3 MLP pools directly (no per-node output).
// fp16 inter-layer storage, fp32 accumulation.
// N=524288 nodes, E=8388608 edges, DIM=32, 8192 graphs x 64 nodes.
// ---------------------------------------------------------------------------

#define NFEAT 16
#define HDIM 32
#define NPG 64
#define BN_EPS 1e-5f
#define ELL_CAP 64

typedef unsigned long long ull;
typedef unsigned int uint;

static constexpr int MAX_NODES = 8192 * 64;
static constexpr int MAX_GRAPHS = 8192;

__device__ __align__(256) uint g_bufA[(size_t)MAX_NODES * HDIM / 2];
__device__ __align__(256) uint g_bufB[(size_t)MAX_NODES * HDIM / 2];
__device__ __align__(256) float g_agg[(size_t)MAX_NODES * HDIM];
__device__ __align__(256) float g_pool[(size_t)MAX_GRAPHS * HDIM];
__device__ int g_cnt[MAX_NODES];
__device__ __align__(16) int g_colell[(size_t)MAX_NODES * ELL_CAP];
__device__ float g_stats[3 * 2 * HDIM];

// ---------------------------------------------------------------------------
// Packed math helpers.
// ---------------------------------------------------------------------------
__device__ __forceinline__ ull pack2(float x, float y) {
    ull r;
    asm("mov.b64 %0, {%1, %2};" : "=l"(r) : "f"(x), "f"(y));
    return r;
}
__device__ __forceinline__ void unpack2(ull v, float& x, float& y) {
    asm("mov.b64 {%0, %1}, %2;" : "=f"(x), "=f"(y) : "l"(v));
}
__device__ __forceinline__ ull fma2(ull a, ull b, ull c) {
    ull d;
    asm("fma.rn.f32x2 %0, %1, %2, %3;" : "=l"(d) : "l"(a), "l"(b), "l"(c));
    return d;
}
__device__ __forceinline__ ull add2(ull a, ull b) {
    ull d;
    asm("add.rn.f32x2 %0, %1, %2;" : "=l"(d) : "l"(a), "l"(b));
    return d;
}
__device__ __forceinline__ void hacc(uint4 u, ull& x0, ull& x1, ull& x2, ull& x3) {
    float2 f;
    f = __half22float2(*(__half2*)&u.x);
    x0 = add2(x0, pack2(f.x, f.y));
    f = __half22float2(*(__half2*)&u.y);
    x1 = add2(x1, pack2(f.x, f.y));
    f = __half22float2(*(__half2*)&u.z);
    x2 = add2(x2, pack2(f.x, f.y));
    f = __half22float2(*(__half2*)&u.w);
    x3 = add2(x3, pack2(f.x, f.y));
}
__device__ __forceinline__ int warp_max_deg(int v) {
    v = max(v, __shfl_xor_sync(0xFFFFFFFFu, v, 4));
    v = max(v, __shfl_xor_sync(0xFFFFFFFFu, v, 8));
    v = max(v, __shfl_xor_sync(0xFFFFFFFFu, v, 16));
    return v;
}

// ---------------------------------------------------------------------------
// ELL build: single pass, 4 edges per thread.
// ---------------------------------------------------------------------------
__global__ void place_kernel(const int4* __restrict__ src4,
                             const int4* __restrict__ dst4,
                             int* __restrict__ cnt, int* __restrict__ colell,
                             int n_edges4) {
    int e = blockIdx.x * blockDim.x + threadIdx.x;
    if (e < n_edges4) {
        int4 s = __ldcs(&src4[e]);
        int4 d = __ldcs(&dst4[e]);
        int p;
        p = min(atomicAdd(&cnt[d.x], 1), ELL_CAP - 1);
        __stcs(&colell[(size_t)d.x * ELL_CAP + p], s.x);
        p = min(atomicAdd(&cnt[d.y], 1), ELL_CAP - 1);
        __stcs(&colell[(size_t)d.y * ELL_CAP + p], s.y);
        p = min(atomicAdd(&cnt[d.z], 1), ELL_CAP - 1);
        __stcs(&colell[(size_t)d.z * ELL_CAP + p], s.z);
        p = min(atomicAdd(&cnt[d.w], 1), ELL_CAP - 1);
        __stcs(&colell[(size_t)d.w * ELL_CAP + p], s.w);
    }
}

// ---------------------------------------------------------------------------
// Gather16 (layer 1, fp32 x): 8 nodes/warp, 4 lanes/node. smem-free.
// ---------------------------------------------------------------------------
__global__ __launch_bounds__(256, 6) void gather16_kernel(
    const ulonglong2* __restrict__ x4, const int* __restrict__ cnt,
    const int* __restrict__ colell, ulonglong2* __restrict__ agg4, int n_nodes) {
    int lane = threadIdx.x & 31;
    int q = lane & 3;
    int w = (blockIdx.x * blockDim.x + threadIdx.x) >> 5;
    int node = w * 8 + (lane >> 2);
    int deg = min(__ldg(&cnt[node]), ELL_CAP);
    int dmax = warp_max_deg(deg);
    const int4* cb4 = (const int4*)(colell + (size_t)node * ELL_CAP);

    ulonglong2 self = __ldg(&x4[(size_t)node * 4 + q]);
    ull a0 = self.x, a1 = self.y;
    ull b0 = 0, b1 = 0;

    for (int b = 0; b < dmax; b += 16) {
        int4 i4 = __ldg(&cb4[(b >> 2) + q]);
#pragma unroll
        for (int j = 0; j < 16; j += 4) {
            int o = j >> 2;
            int s0 = __shfl_sync(0xFFFFFFFFu, i4.x, o, 4);
            int s1 = __shfl_sync(0xFFFFFFFFu, i4.y, o, 4);
            int s2 = __shfl_sync(0xFFFFFFFFu, i4.z, o, 4);
            int s3 = __shfl_sync(0xFFFFFFFFu, i4.w, o, 4);
            if (b + j + 0 < deg) {
                ulonglong2 u = __ldg(&x4[(size_t)s0 * 4 + q]);
                a0 = add2(a0, u.x);
                a1 = add2(a1, u.y);
            }
            if (b + j + 1 < deg) {
                ulonglong2 u = __ldg(&x4[(size_t)s1 * 4 + q]);
                b0 = add2(b0, u.x);
                b1 = add2(b1, u.y);
            }
            if (b + j + 2 < deg) {
                ulonglong2 u = __ldg(&x4[(size_t)s2 * 4 + q]);
                a0 = add2(a0, u.x);
                a1 = add2(a1, u.y);
            }
            if (b + j + 3 < deg) {
                ulonglong2 u = __ldg(&x4[(size_t)s3 * 4 + q]);
                b0 = add2(b0, u.x);
                b1 = add2(b1, u.y);
            }
        }
    }
    ulonglong2 outv;
    outv.x = add2(a0, b0);
    outv.y = add2(a1, b1);
    agg4[(size_t)node * 4 + q] = outv;
}

// ---------------------------------------------------------------------------
// Gather32h (layers 2/3): fp16 rows in, fp32 accumulate, fp32 agg out.
// ---------------------------------------------------------------------------
__global__ __launch_bounds__(256, 6) void gather32h_kernel(
    const uint4* __restrict__ vinh4, const int* __restrict__ cnt,
    const int* __restrict__ colell, ulonglong2* __restrict__ agg4, int n_nodes) {
    int lane = threadIdx.x & 31;
    int q = lane & 3;
    int w = (blockIdx.x * blockDim.x + threadIdx.x) >> 5;
    int node = w * 8 + (lane >> 2);
    int deg = min(__ldg(&cnt[node]), ELL_CAP);
    int dmax = warp_max_deg(deg);
    const int4* cb4 = (const int4*)(colell + (size_t)node * ELL_CAP);

    ull a0 = 0, a1 = 0, a2 = 0, a3 = 0;
    ull b0 = 0, b1 = 0, b2 = 0, b3 = 0;
    hacc(__ldg(&vinh4[(size_t)node * 4 + q]), a0, a1, a2, a3);  // self

    for (int b = 0; b < dmax; b += 16) {
        int4 i4 = __ldg(&cb4[(b >> 2) + q]);
#pragma unroll
        for (int j = 0; j < 16; j += 4) {
            int o = j >> 2;
            int s0 = __shfl_sync(0xFFFFFFFFu, i4.x, o, 4);
            int s1 = __shfl_sync(0xFFFFFFFFu, i4.y, o, 4);
            int s2 = __shfl_sync(0xFFFFFFFFu, i4.z, o, 4);
            int s3 = __shfl_sync(0xFFFFFFFFu, i4.w, o, 4);
            if (b + j + 0 < deg) hacc(__ldg(&vinh4[(size_t)s0 * 4 + q]), a0, a1, a2, a3);
            if (b + j + 1 < deg) hacc(__ldg(&vinh4[(size_t)s1 * 4 + q]), b0, b1, b2, b3);
            if (b + j + 2 < deg) hacc(__ldg(&vinh4[(size_t)s2 * 4 + q]), a0, a1, a2, a3);
            if (b + j + 3 < deg) hacc(__ldg(&vinh4[(size_t)s3 * 4 + q]), b0, b1, b2, b3);
        }
    }
    ulonglong2 o0, o1;
    o0.x = add2(a0, b0);
    o0.y = add2(a1, b1);
    o1.x = add2(a2, b2);
    o1.y = add2(a3, b3);
    agg4[(size_t)node * 8 + 2 * q] = o0;
    agg4[(size_t)node * 8 + 2 * q + 1] = o1;
}

// ---------------------------------------------------------------------------
// MLP16 (layer 1): fp32 16-dim agg in, fp16 32-dim out. Stats fused.
// ---------------------------------------------------------------------------
__global__ __launch_bounds__(256) void mlp16_kernel(
    const float* __restrict__ agg, const float* __restrict__ Wa,
    const float* __restrict__ ba, const float* __restrict__ Wb,
    const float* __restrict__ bb, uint* __restrict__ vouth,
    float* __restrict__ stats, int n_nodes) {
    __shared__ float tile[256 * 33];
    __shared__ __align__(16) ull sWa2[NFEAT * HDIM / 2];
    __shared__ __align__(16) ull sWb2[HDIM * HDIM / 2];
    __shared__ float sba[HDIM], sbb[HDIM];
    __shared__ float ps[8 * 32], pq[8 * 32];

    for (int i = threadIdx.x; i < NFEAT * HDIM / 2; i += 256)
        sWa2[i] = ((const ull*)Wa)[i];
    for (int i = threadIdx.x; i < HDIM * HDIM / 2; i += 256)
        sWb2[i] = ((const ull*)Wb)[i];
    if (threadIdx.x < HDIM) {
        sba[threadIdx.x] = ba[threadIdx.x];
        sbb[threadIdx.x] = bb[threadIdx.x];
    }
    __syncthreads();

    int warp = threadIdx.x >> 5;
    int lane = threadIdx.x & 31;
    int base = blockIdx.x * 256;
    int tid = threadIdx.x;

    size_t lim = (size_t)n_nodes * NFEAT;
#pragma unroll
    for (int off = 0; off < 16; off++) {
        int idx = off * 256 + tid;
        int row = idx >> 4, ch = idx & 15;
        size_t g = (size_t)base * NFEAT + idx;
        tile[row * 33 + ch] = (g < lim) ? __ldcs(&agg[g]) : 0.0f;
    }
    __syncthreads();

    bool valid = (base + tid) < n_nodes;
    float t[NFEAT];
#pragma unroll
    for (int i = 0; i < NFEAT; i++) t[i] = tile[tid * 33 + i];

    ull u2[16];
#pragma unroll
    for (int j = 0; j < 16; j++) u2[j] = pack2(sba[2 * j], sba[2 * j + 1]);
#pragma unroll
    for (int i = 0; i < NFEAT; i++) {
        ull tt = pack2(t[i], t[i]);
#pragma unroll
        for (int j = 0; j < 8; j++) {
            ulonglong2 w = *(const ulonglong2*)&sWa2[i * 16 + 2 * j];
            u2[2 * j] = fma2(tt, w.x, u2[2 * j]);
            u2[2 * j + 1] = fma2(tt, w.y, u2[2 * j + 1]);
        }
    }
    float uu[HDIM];
#pragma unroll
    for (int j = 0; j < 16; j++) {
        float a, b;
        unpack2(u2[j], a, b);
        uu[2 * j] = fmaxf(a, 0.0f);
        uu[2 * j + 1] = fmaxf(b, 0.0f);
    }
    ull v2[16];
#pragma unroll
    for (int j = 0; j < 16; j++) v2[j] = pack2(sbb[2 * j], sbb[2 * j + 1]);
#pragma unroll
    for (int i = 0; i < HDIM; i++) {
        ull tt = pack2(uu[i], uu[i]);
#pragma unroll
        for (int j = 0; j < 8; j++) {
            ulonglong2 w = *(const ulonglong2*)&sWb2[i * 16 + 2 * j];
            v2[2 * j] = fma2(tt, w.x, v2[2 * j]);
            v2[2 * j + 1] = fma2(tt, w.y, v2[2 * j + 1]);
        }
    }
#pragma unroll
    for (int j = 0; j < 16; j++) {
        float a, b;
        unpack2(v2[j], a, b);
        tile[tid * 33 + 2 * j] = valid ? fmaxf(a, 0.0f) : 0.0f;
        tile[tid * 33 + 2 * j + 1] = valid ? fmaxf(b, 0.0f) : 0.0f;
    }
    __syncthreads();

#pragma unroll
    for (int k = 0; k < 16; k++) {
        int rr = warp * 32 + 2 * k + (lane >> 4);
        int node = base + rr;
        int wd = lane & 15;
        if (node < n_nodes) {
            float2 f;
            f.x = tile[rr * 33 + 2 * wd];
            f.y = tile[rr * 33 + 2 * wd + 1];
            __half2 h = __float22half2_rn(f);
            vouth[(size_t)node * 16 + wd] = *(uint*)&h;
        }
    }
    float s = 0.0f, q = 0.0f;
#pragma unroll
    for (int k = 0; k < 32; k++) {
        float vv = tile[(warp * 32 + k) * 33 + lane];
        s += vv;
        q += vv * vv;
    }
    ps[warp * 32 + lane] = s;
    pq[warp * 32 + lane] = q;
    __syncthreads();
    if (tid < 32) {
        float ss = 0.0f, qq = 0.0f;
#pragma unroll
        for (int k = 0; k < 8; k++) {
            ss += ps[k * 32 + tid];
            qq += pq[k * 32 + tid];
        }
        atomicAdd(&stats[tid], ss);
        atomicAdd(&stats[32 + tid], qq);
    }
}

// ---------------------------------------------------------------------------
// MLP (layers 2/3): fp32 agg in; prev BN folded in-kernel.
// POOL=false: fp16 per-node output. POOL=true: per-graph channel sums
// (block = 256 nodes = exactly 4 graphs of 64) -> pooled[], no node output.
// ---------------------------------------------------------------------------
template <bool POOL>
__global__ __launch_bounds__(256) void mlp_kernel(
    const float* __restrict__ agg, const int* __restrict__ cnt,
    const float* __restrict__ pstats, const float* __restrict__ pgamma,
    const float* __restrict__ pbeta, const float* __restrict__ Wa,
    const float* __restrict__ ba, const float* __restrict__ Wb,
    const float* __restrict__ bb, uint* __restrict__ vouth,
    float* __restrict__ pooled, float* __restrict__ stats, float invN,
    int n_nodes) {
    __shared__ float tile[256 * 33];
    __shared__ __align__(16) ull sWa2[HDIM * HDIM / 2];
    __shared__ __align__(16) ull sWb2[HDIM * HDIM / 2];
    __shared__ float sba[HDIM], sbb[HDIM], scv[HDIM];
    __shared__ float ssc[HDIM], ssh[HDIM];
    __shared__ float ps[8 * 32], pq[8 * 32];

    int tid = threadIdx.x;
    if (tid < HDIM) {
        float m = pstats[tid] * invN;
        float var = pstats[HDIM + tid] * invN - m * m;
        float sc = pgamma[tid] * rsqrtf(var + BN_EPS);
        ssc[tid] = sc;
        ssh[tid] = pbeta[tid] - m * sc;
        sba[tid] = ba[tid];
        sbb[tid] = bb[tid];
    }
    __syncthreads();
    for (int p = tid; p < HDIM * HDIM / 2; p += 256) {
        float sc = ssc[p >> 4];
        sWa2[p] = pack2(sc * Wa[2 * p], sc * Wa[2 * p + 1]);
        sWb2[p] = ((const ull*)Wb)[p];
    }
    if (tid < HDIM) {
        float c = 0.0f;
#pragma unroll
        for (int i = 0; i < HDIM; i++) c = fmaf(ssh[i], __ldg(&Wa[i * HDIM + tid]), c);
        scv[tid] = c;
    }
    __syncthreads();

    int warp = tid >> 5;
    int lane = tid & 31;
    int base = blockIdx.x * 256;

    for (int k = 0; k < 32; k++) {
        int row = warp * 32 + k;
        int node = base + row;
        tile[row * 33 + lane] =
            (node < n_nodes) ? __ldcs(&agg[(size_t)node * HDIM + lane]) : 0.0f;
    }
    __syncthreads();

    bool valid = (base + tid) < n_nodes;
    float degp1 = 1.0f;
    if (valid) degp1 = (float)cnt[base + tid] + 1.0f;
    ull u2[16];
#pragma unroll
    for (int j = 0; j < 16; j++)
        u2[j] = pack2(fmaf(degp1, scv[2 * j], sba[2 * j]),
                      fmaf(degp1, scv[2 * j + 1], sba[2 * j + 1]));
#pragma unroll
    for (int i = 0; i < HDIM; i++) {
        float ti = tile[tid * 33 + i];
        ull tt = pack2(ti, ti);
#pragma unroll
        for (int j = 0; j < 8; j++) {
            ulonglong2 w = *(const ulonglong2*)&sWa2[i * 16 + 2 * j];
            u2[2 * j] = fma2(tt, w.x, u2[2 * j]);
            u2[2 * j + 1] = fma2(tt, w.y, u2[2 * j + 1]);
        }
    }
    float uu[HDIM];
#pragma unroll
    for (int j = 0; j < 16; j++) {
        float a, b;
        unpack2(u2[j], a, b);
        uu[2 * j] = fmaxf(a, 0.0f);
        uu[2 * j + 1] = fmaxf(b, 0.0f);
    }
    ull v2[16];
#pragma unroll
    for (int j = 0; j < 16; j++) v2[j] = pack2(sbb[2 * j], sbb[2 * j + 1]);
#pragma unroll
    for (int i = 0; i < HDIM; i++) {
        ull tt = pack2(uu[i], uu[i]);
#pragma unroll
        for (int j = 0; j < 8; j++) {
            ulonglong2 w = *(const ulonglong2*)&sWb2[i * 16 + 2 * j];
            v2[2 * j] = fma2(tt, w.x, v2[2 * j]);
            v2[2 * j + 1] = fma2(tt, w.y, v2[2 * j + 1]);
        }
    }
#pragma unroll
    for (int j = 0; j < 16; j++) {
        float a, b;
        unpack2(v2[j], a, b);
        tile[tid * 33 + 2 * j] = valid ? fmaxf(a, 0.0f) : 0.0f;
        tile[tid * 33 + 2 * j + 1] = valid ? fmaxf(b, 0.0f) : 0.0f;
    }
    __syncthreads();

    if (!POOL) {
#pragma unroll
        for (int k = 0; k < 16; k++) {
            int rr = warp * 32 + 2 * k + (lane >> 4);
            int node = base + rr;
            int wd = lane & 15;
            if (node < n_nodes) {
                float2 f;
                f.x = tile[rr * 33 + 2 * wd];
                f.y = tile[rr * 33 + 2 * wd + 1];
                __half2 h = __float22half2_rn(f);
                vouth[(size_t)node * 16 + wd] = *(uint*)&h;
            }
        }
    }
    float s = 0.0f, q = 0.0f;
#pragma unroll
    for (int k = 0; k < 32; k++) {
        float vv = tile[(warp * 32 + k) * 33 + lane];
        s += vv;
        q += vv * vv;
    }
    ps[warp * 32 + lane] = s;
    pq[warp * 32 + lane] = q;
    __syncthreads();
    if (tid < 32) {
        float ss = 0.0f, qq = 0.0f;
#pragma unroll
        for (int k = 0; k < 8; k++) {
            ss += ps[k * 32 + tid];
            qq += pq[k * 32 + tid];
        }
        atomicAdd(&stats[tid], ss);
        atomicAdd(&stats[32 + tid], qq);
    }
    if (POOL) {
        // Block covers graphs [base/64, base/64+4); graph j = warps 2j,2j+1.
        if (tid < 128) {
            int j = tid >> 5;
            int ch = tid & 31;
            int graph = (base >> 6) + j;
            pooled[(size_t)graph * HDIM + ch] =
                ps[(2 * j) * 32 + ch] + ps[(2 * j + 1) * 32 + ch];
        }
    }
}

// ---------------------------------------------------------------------------
// Head: BN3 from stats, applied to pooled sums; 32->2 linear + log_softmax.
// Warp per graph (reads 1MB pooled, trivial).
// ---------------------------------------------------------------------------
__global__ void head_kernel(const float* __restrict__ pooled,
                            const float* __restrict__ pstats,
                            const float* __restrict__ pgamma,
                            const float* __restrict__ pbeta,
                            const float* __restrict__ Wf, const float* __restrict__ bf,
                            float* __restrict__ out, float invN, int n_graphs) {
    __shared__ float ssc[HDIM], ssh[HDIM];
    if (threadIdx.x < HDIM) {
        float m = pstats[threadIdx.x] * invN;
        float var = pstats[HDIM + threadIdx.x] * invN - m * m;
        float sc = pgamma[threadIdx.x] * rsqrtf(var + BN_EPS);
        ssc[threadIdx.x] = sc;
        ssh[threadIdx.x] = pbeta[threadIdx.x] - m * sc;
    }
    __syncthreads();
    int g = (blockIdx.x * blockDim.x + threadIdx.x) >> 5;
    int lane = threadIdx.x & 31;
    if (g >= n_graphs) return;
    float s = pooled[(size_t)g * HDIM + lane];
    s = ssc[lane] * s + (float)NPG * ssh[lane];
    float p0 = s * Wf[lane * 2 + 0];
    float p1 = s * Wf[lane * 2 + 1];
#pragma unroll
    for (int off = 16; off > 0; off >>= 1) {
        p0 += __shfl_xor_sync(0xFFFFFFFFu, p0, off);
        p1 += __shfl_xor_sync(0xFFFFFFFFu, p1, off);
    }
    if (lane == 0) {
        float l0 = p0 + bf[0];
        float l1 = p1 + bf[1];
        float m = fmaxf(l0, l1);
        float lse = m + logf(expf(l0 - m) + expf(l1 - m));
        out[g * 2 + 0] = l0 - lse;
        out[g * 2 + 1] = l1 - lse;
    }
}

// ---------------------------------------------------------------------------
// Launch. Kernel order: place(1), gather16(2), mlp16(3), gather32h(4) <- ncu.
// ---------------------------------------------------------------------------
extern "C" void kernel_launch(void* const* d_in, const int* in_sizes, int n_in,
                              void* d_out, int out_size) {
    const float* x   = (const float*)d_in[0];
    const int*   ei  = (const int*)d_in[1];
    const float* W1a = (const float*)d_in[3];
    const float* b1a = (const float*)d_in[4];
    const float* W1b = (const float*)d_in[5];
    const float* b1b = (const float*)d_in[6];
    const float* W2a = (const float*)d_in[7];
    const float* b2a = (const float*)d_in[8];
    const float* W2b = (const float*)d_in[9];
    const float* b2b = (const float*)d_in[10];
    const float* W3a = (const float*)d_in[11];
    const float* b3a = (const float*)d_in[12];
    const float* W3b = (const float*)d_in[13];
    const float* b3b = (const float*)d_in[14];
    const float* g1  = (const float*)d_in[15];
    const float* be1 = (const float*)d_in[16];
    const float* g2  = (const float*)d_in[17];
    const float* be2 = (const float*)d_in[18];
    const float* g3  = (const float*)d_in[19];
    const float* be3 = (const float*)d_in[20];
    const float* Wf  = (const float*)d_in[21];
    const float* bf  = (const float*)d_in[22];
    float* out = (float*)d_out;

    int n_nodes  = in_sizes[0] / NFEAT;
    int n_edges  = in_sizes[1] / 2;
    int n_graphs = n_nodes / NPG;
    const int* src = ei;
    const int* dst = ei + n_edges;

    float *agg, *stats, *pooled;
    uint *bufA, *bufB;
    int *cnt, *colell;
    cudaGetSymbolAddress((void**)&bufA, g_bufA);
    cudaGetSymbolAddress((void**)&bufB, g_bufB);
    cudaGetSymbolAddress((void**)&agg, g_agg);
    cudaGetSymbolAddress((void**)&pooled, g_pool);
    cudaGetSymbolAddress((void**)&stats, g_stats);
    cudaGetSymbolAddress((void**)&cnt, g_cnt);
    cudaGetSymbolAddress((void**)&colell, g_colell);

    float invN = 1.0f / (float)n_nodes;
    int n_edges4 = n_edges / 4;
    int grid_e4 = (n_edges4 + 255) / 256;
    int grid_n = (n_nodes + 255) / 256;
    int grid_g = (n_nodes * 4 + 255) / 256;

    // ---- ELL build ----
    cudaMemsetAsync(cnt, 0, (size_t)n_nodes * sizeof(int), 0);
    cudaMemsetAsync(stats, 0, 6 * HDIM * sizeof(float), 0);
    place_kernel<<<grid_e4, 256>>>((const int4*)src, (const int4*)dst,
                                   cnt, colell, n_edges4);           // k1

    // ---- Layer 1 ----
    gather16_kernel<<<grid_g, 256>>>((const ulonglong2*)x, cnt, colell,
                                     (ulonglong2*)agg, n_nodes);     // k2
    mlp16_kernel<<<grid_n, 256>>>(agg, W1a, b1a, W1b, b1b, bufA,
                                  stats + 0, n_nodes);               // k3

    // ---- Layer 2 (BN1 folded in-kernel) ----
    gather32h_kernel<<<grid_g, 256>>>((const uint4*)bufA, cnt, colell,
                                      (ulonglong2*)agg, n_nodes);    // k4 <- ncu
    mlp_kernel<false><<<grid_n, 256>>>(agg, cnt, stats + 0, g1, be1, W2a, b2a,
                                       W2b, b2b, bufB, nullptr,
                                       stats + 64, invN, n_nodes);

    // ---- Layer 3 (BN2 folded; pooling fused, no per-node output) ----
    gather32h_kernel<<<grid_g, 256>>>((const uint4*)bufB, cnt, colell,
                                      (ulonglong2*)agg, n_nodes);
    mlp_kernel<true><<<grid_n, 256>>>(agg, cnt, stats + 64, g2, be2, W3a, b3a,
                                      W3b, b3b, nullptr, pooled,
                                      stats + 128, invN, n_nodes);

    // ---- Head (BN3 folded) ----
    int grid_p = (n_graphs * 32 + 255) / 256;
    head_kernel<<<grid_p, 256>>>(pooled, stats + 128, g3, be3,
                                 Wf, bf, out, invN, n_graphs);
}